// round 1
// baseline (speedup 1.0000x reference)
#include <cuda_runtime.h>
#include <cuda_bf16.h>
#include <mma.h>

using namespace nvcuda;

#define BB 8
#define SS 4096
#define DD 1024
#define HH 16
#define KK 256
#define DH 64
#define MM (BB*SS)

// Scratch (device globals: allocation-free per harness rules)
__device__ float g_tmp[(size_t)MM * DD];           // hk, then hv
__device__ float g_q  [(size_t)MM * DD];           // q
__device__ float g_hkp[(size_t)BB * KK * DD];      // projected K
__device__ float g_hvp[(size_t)BB * KK * DD];      // projected V
__device__ int   g_len[BB];
__device__ float g_isl[BB];

// ---------------------------------------------------------------------------
// lengths[b] = count(mask[b,0,0,:] > -1), inv_sqrt_len
// ---------------------------------------------------------------------------
__global__ void k_lengths(const float* __restrict__ mask) {
    int b = blockIdx.x;
    __shared__ int cnt;
    if (threadIdx.x == 0) cnt = 0;
    __syncthreads();
    int local = 0;
    for (int s = threadIdx.x; s < SS; s += blockDim.x)
        if (mask[(size_t)b * SS + s] > -1.0f) local++;
    atomicAdd(&cnt, local);
    __syncthreads();
    if (threadIdx.x == 0) {
        g_len[b] = cnt;
        g_isl[b] = rsqrtf((float)cnt);
    }
}

// ---------------------------------------------------------------------------
// C[M,N] = A[M,Kd] * W[N,Kd]^T + bias[N]   (TF32 wmma, fp32 accumulate)
// Block tile 128x128, BK=16, 8 warps (2x4), warp tile 64x32 (4x2 frags)
// ---------------------------------------------------------------------------
__global__ __launch_bounds__(256) void k_gemm_nt_tc(
    const float* __restrict__ A, const float* __restrict__ W,
    const float* __restrict__ bias, float* __restrict__ C,
    int Ndim, int Kd)
{
    __shared__ float As[128 * 16];  // [m][k], ld=16
    __shared__ float Bs[128 * 16];  // [n][k], ld=16
    int tid = threadIdx.x;
    int warp = tid >> 5, lane = tid & 31;
    int wm = warp & 1, wn = warp >> 1;
    int m0 = blockIdx.y * 128, n0 = blockIdx.x * 128;

    wmma::fragment<wmma::accumulator, 16, 16, 8, float> acc[4][2];
#pragma unroll
    for (int i = 0; i < 4; i++)
#pragma unroll
        for (int j = 0; j < 2; j++)
            wmma::fill_fragment(acc[i][j], 0.0f);

    for (int k0 = 0; k0 < Kd; k0 += 16) {
#pragma unroll
        for (int it = 0; it < 2; it++) {
            int f4 = tid + it * 256;        // 512 float4 = 128x16 floats
            int row = f4 >> 2, c4 = f4 & 3;
            ((float4*)As)[f4] = *(const float4*)&A[(size_t)(m0 + row) * Kd + k0 + c4 * 4];
            ((float4*)Bs)[f4] = *(const float4*)&W[(size_t)(n0 + row) * Kd + k0 + c4 * 4];
        }
        __syncthreads();
#pragma unroll
        for (int ksub = 0; ksub < 2; ksub++) {
            wmma::fragment<wmma::matrix_a, 16, 16, 8, wmma::precision::tf32, wmma::row_major> af[4];
            wmma::fragment<wmma::matrix_b, 16, 16, 8, wmma::precision::tf32, wmma::col_major> bf[2];
#pragma unroll
            for (int i = 0; i < 4; i++) {
                wmma::load_matrix_sync(af[i], &As[(wm * 64 + i * 16) * 16 + ksub * 8], 16);
#pragma unroll
                for (int e = 0; e < af[i].num_elements; e++)
                    af[i].x[e] = wmma::__float_to_tf32(af[i].x[e]);
            }
#pragma unroll
            for (int j = 0; j < 2; j++) {
                wmma::load_matrix_sync(bf[j], &Bs[(wn * 32 + j * 16) * 16 + ksub * 8], 16);
#pragma unroll
                for (int e = 0; e < bf[j].num_elements; e++)
                    bf[j].x[e] = wmma::__float_to_tf32(bf[j].x[e]);
            }
#pragma unroll
            for (int i = 0; i < 4; i++)
#pragma unroll
                for (int j = 0; j < 2; j++)
                    wmma::mma_sync(acc[i][j], af[i], bf[j], acc[i][j]);
        }
        __syncthreads();
    }

    // Epilogue: stage per-warp 16x16 in smem, write with bias
    float* stage = As + warp * 256;
#pragma unroll
    for (int i = 0; i < 4; i++)
#pragma unroll
        for (int j = 0; j < 2; j++) {
            wmma::store_matrix_sync(stage, acc[i][j], 16, wmma::mem_row_major);
            __syncwarp();
            int gr0 = m0 + wm * 64 + i * 16;
            int gc0 = n0 + wn * 32 + j * 16;
#pragma unroll
            for (int e = 0; e < 8; e++) {
                int idx = lane * 8 + e;
                int r = idx >> 4, c = idx & 15;
                C[(size_t)(gr0 + r) * Ndim + gc0 + c] = stage[r * 16 + c] + bias[gc0 + c];
            }
            __syncwarp();
        }
}

// ---------------------------------------------------------------------------
// Out[b,k,d] = isl[b] * sum_{s<len[b]} P[s,k] * H[b,s,d]    (TF32 wmma)
// A(m=k, kdim=s) = P[s,k] masked; staged col-major. B(kdim=s, n=d) row-major.
// ---------------------------------------------------------------------------
__global__ __launch_bounds__(256) void k_proj_tc(
    const float* __restrict__ P,     // (S, K)
    const float* __restrict__ Hsrc,  // (B, S, D)
    float* __restrict__ Out)         // (B, K, D)
{
    __shared__ float Acm[16 * 128];  // [ss][m] (col-major for matrix_a, ld=128)
    __shared__ float Bsm[16 * 128];  // [ss][n] (row-major for matrix_b, ld=128)
    int tid = threadIdx.x;
    int warp = tid >> 5, lane = tid & 31;
    int wm = warp & 1, wn = warp >> 1;
    int b = blockIdx.z;
    int m0 = blockIdx.y * 128, n0 = blockIdx.x * 128;
    int len = g_len[b];
    float isl = g_isl[b];
    const float* H = Hsrc + (size_t)b * SS * DD;

    wmma::fragment<wmma::accumulator, 16, 16, 8, float> acc[4][2];
#pragma unroll
    for (int i = 0; i < 4; i++)
#pragma unroll
        for (int j = 0; j < 2; j++)
            wmma::fill_fragment(acc[i][j], 0.0f);

    for (int s0 = 0; s0 < len; s0 += 16) {
#pragma unroll
        for (int it = 0; it < 2; it++) {
            int f4 = tid + it * 256;        // 512 f4 = 16x128 floats
            int ss = f4 >> 5, m4 = f4 & 31;
            int s = s0 + ss;                // always < SS (SS multiple of 16)
            float4 av;
            if (s < len) av = *(const float4*)&P[(size_t)s * KK + m0 + m4 * 4];
            else         av = make_float4(0.f, 0.f, 0.f, 0.f);
            ((float4*)Acm)[ss * 32 + m4] = av;
            ((float4*)Bsm)[ss * 32 + m4] = *(const float4*)&H[(size_t)s * DD + n0 + m4 * 4];
        }
        __syncthreads();
#pragma unroll
        for (int ksub = 0; ksub < 2; ksub++) {
            wmma::fragment<wmma::matrix_a, 16, 16, 8, wmma::precision::tf32, wmma::col_major> af[4];
            wmma::fragment<wmma::matrix_b, 16, 16, 8, wmma::precision::tf32, wmma::row_major> bf[2];
#pragma unroll
            for (int i = 0; i < 4; i++) {
                wmma::load_matrix_sync(af[i], &Acm[ksub * 8 * 128 + wm * 64 + i * 16], 128);
#pragma unroll
                for (int e = 0; e < af[i].num_elements; e++)
                    af[i].x[e] = wmma::__float_to_tf32(af[i].x[e]);
            }
#pragma unroll
            for (int j = 0; j < 2; j++) {
                wmma::load_matrix_sync(bf[j], &Bsm[ksub * 8 * 128 + wn * 32 + j * 16], 128);
#pragma unroll
                for (int e = 0; e < bf[j].num_elements; e++)
                    bf[j].x[e] = wmma::__float_to_tf32(bf[j].x[e]);
            }
#pragma unroll
            for (int i = 0; i < 4; i++)
#pragma unroll
                for (int j = 0; j < 2; j++)
                    wmma::mma_sync(acc[i][j], af[i], bf[j], acc[i][j]);
        }
        __syncthreads();
    }

    float* stage = Acm + warp * 256;
#pragma unroll
    for (int i = 0; i < 4; i++)
#pragma unroll
        for (int j = 0; j < 2; j++) {
            wmma::store_matrix_sync(stage, acc[i][j], 16, wmma::mem_row_major);
            __syncwarp();
            int gr0 = m0 + wm * 64 + i * 16;
            int gc0 = n0 + wn * 32 + j * 16;
#pragma unroll
            for (int e = 0; e < 8; e++) {
                int idx = lane * 8 + e;
                int r = idx >> 4, c = idx & 15;
                Out[((size_t)b * KK + gr0 + r) * DD + gc0 + c] = stage[r * 16 + c] * isl;
            }
            __syncwarp();
        }
}

// ---------------------------------------------------------------------------
// Fused attention per (b, h, 64-query tile): scores -> softmax -> ctx (fp32)
// smem: K(256x64) + V(256x64) + Q(64x65 pad) + scores(64x257 pad) = 208.5 KB
// ---------------------------------------------------------------------------
__global__ __launch_bounds__(256, 1) void k_attn(
    const float* __restrict__ q, const float* __restrict__ kp,
    const float* __restrict__ vp, float* __restrict__ out)
{
    extern __shared__ float sm[];
    float* ks = sm;                    // 256*64
    float* vs = ks + KK * DH;          // 256*64
    float* qs = vs + KK * DH;          // 64*65
    float* sc = qs + 64 * 65;          // 64*257

    int qt = blockIdx.x, h = blockIdx.y, b = blockIdx.z;
    int s0 = qt * 64;
    int tid = threadIdx.x;

    // Load K/V tiles (coalesced float4; reads are warp-broadcast later)
    for (int i = tid; i < KK * 16; i += 256) {
        int kidx = i >> 4, c4 = i & 15;
        size_t off = ((size_t)b * KK + kidx) * DD + h * DH + c4 * 4;
        ((float4*)ks)[i] = *(const float4*)&kp[off];
        ((float4*)vs)[i] = *(const float4*)&vp[off];
    }
    // Load Q tile with ld=65 padding (conflict-free per-lane row reads)
    for (int i = tid; i < 64 * 16; i += 256) {
        int r = i >> 4, c4 = i & 15;
        float4 v = *(const float4*)&q[((size_t)b * SS + s0 + r) * DD + h * DH + c4 * 4];
        float* dst = &qs[r * 65 + c4 * 4];
        dst[0] = v.x; dst[1] = v.y; dst[2] = v.z; dst[3] = v.w;
    }
    __syncthreads();

    int qi = tid & 63, grp = tid >> 6;

    // Phase 1: scores[qi, grp*64 .. grp*64+63]
    {
        float qr[64];
#pragma unroll
        for (int d = 0; d < 64; d++) qr[d] = qs[qi * 65 + d];
#pragma unroll 2
        for (int kk = 0; kk < 64; kk++) {
            int k = grp * 64 + kk;
            const float4* krow = (const float4*)&ks[k * DH];
            float a0 = 0.f, a1 = 0.f, a2 = 0.f, a3 = 0.f;
#pragma unroll
            for (int d4 = 0; d4 < 16; d4++) {
                float4 kv = krow[d4];
                a0 += qr[d4 * 4 + 0] * kv.x;
                a1 += qr[d4 * 4 + 1] * kv.y;
                a2 += qr[d4 * 4 + 2] * kv.z;
                a3 += qr[d4 * 4 + 3] * kv.w;
            }
            sc[qi * 257 + k] = (a0 + a1 + a2 + a3) * 0.125f;   // 1/sqrt(64)
        }
    }
    __syncthreads();

    // Phase 2: softmax over K=256, one thread per row
    if (tid < 64) {
        float mx = -3.0e38f;
#pragma unroll 4
        for (int k = 0; k < KK; k++) mx = fmaxf(mx, sc[tid * 257 + k]);
        float sum = 0.f;
#pragma unroll 4
        for (int k = 0; k < KK; k++) {
            float e = __expf(sc[tid * 257 + k] - mx);
            sc[tid * 257 + k] = e;
            sum += e;
        }
        float inv = 1.0f / sum;
#pragma unroll 4
        for (int k = 0; k < KK; k++) sc[tid * 257 + k] *= inv;
    }
    __syncthreads();

    // Phase 3: ctx[qi, grp*16 .. grp*16+15] = P @ V
    {
        float o[16];
#pragma unroll
        for (int i = 0; i < 16; i++) o[i] = 0.f;
#pragma unroll 2
        for (int k = 0; k < KK; k++) {
            float p = sc[qi * 257 + k];
            const float4* vrow = (const float4*)&vs[k * DH + grp * 16];
#pragma unroll
            for (int i4 = 0; i4 < 4; i4++) {
                float4 vv = vrow[i4];
                o[i4 * 4 + 0] += p * vv.x;
                o[i4 * 4 + 1] += p * vv.y;
                o[i4 * 4 + 2] += p * vv.z;
                o[i4 * 4 + 3] += p * vv.w;
            }
        }
        float4* op = (float4*)&out[((size_t)b * SS + s0 + qi) * DD + h * DH + grp * 16];
        op[0] = make_float4(o[0],  o[1],  o[2],  o[3]);
        op[1] = make_float4(o[4],  o[5],  o[6],  o[7]);
        op[2] = make_float4(o[8],  o[9],  o[10], o[11]);
        op[3] = make_float4(o[12], o[13], o[14], o[15]);
    }
}

// ---------------------------------------------------------------------------
extern "C" void kernel_launch(void* const* d_in, const int* in_sizes, int n_in,
                              void* d_out, int out_size)
{
    const float* X    = (const float*)d_in[0];
    const float* mask = (const float*)d_in[1];
    const float* Wq   = (const float*)d_in[2];
    const float* bq   = (const float*)d_in[3];
    const float* Wk   = (const float*)d_in[4];
    const float* bk   = (const float*)d_in[5];
    const float* Wv   = (const float*)d_in[6];
    const float* bv   = (const float*)d_in[7];
    const float* pk   = (const float*)d_in[8];
    const float* pv   = (const float*)d_in[9];
    float* out = (float*)d_out;

    float *tmp, *qb, *hkp, *hvp;
    cudaGetSymbolAddress((void**)&tmp, g_tmp);
    cudaGetSymbolAddress((void**)&qb,  g_q);
    cudaGetSymbolAddress((void**)&hkp, g_hkp);
    cudaGetSymbolAddress((void**)&hvp, g_hvp);

    const int ATTN_SMEM = (KK * DH + KK * DH + 64 * 65 + 64 * 257) * 4;
    cudaFuncSetAttribute(k_attn, cudaFuncAttributeMaxDynamicSharedMemorySize, ATTN_SMEM);

    k_lengths<<<BB, 256>>>(mask);

    dim3 gg(DD / 128, MM / 128);
    dim3 gp(DD / 128, KK / 128, BB);

    k_gemm_nt_tc<<<gg, 256>>>(X, Wk, bk, tmp, DD, DD);   // hk
    k_proj_tc  <<<gp, 256>>>(pk, tmp, hkp);              // hkp
    k_gemm_nt_tc<<<gg, 256>>>(X, Wv, bv, tmp, DD, DD);   // hv
    k_proj_tc  <<<gp, 256>>>(pv, tmp, hvp);              // hvp
    k_gemm_nt_tc<<<gg, 256>>>(X, Wq, bq, qb, DD, DD);    // q

    k_attn<<<dim3(SS / 64, HH, BB), 256, ATTN_SMEM>>>(qb, hkp, hvp, out);
}

// round 2
// speedup vs baseline: 1.2556x; 1.2556x over previous
#include <cuda_runtime.h>
#include <cuda_bf16.h>
#include <mma.h>

using namespace nvcuda;

#define BB 8
#define SS 4096
#define DD 1024
#define HH 16
#define KK 256
#define DH 64
#define MM (BB*SS)

// Scratch (device globals: allocation-free per harness rules)
__device__ float g_hk [(size_t)MM * DD];
__device__ float g_hv [(size_t)MM * DD];
__device__ float g_q  [(size_t)MM * DD];
__device__ float g_hkp[(size_t)BB * KK * DD];
__device__ float g_hvp[(size_t)BB * KK * DD];
__device__ int   g_len[BB];
__device__ float g_isl[BB];

// ---------------------------------------------------------------------------
// lengths[b] = count(mask[b,0,0,:] > -1), inv_sqrt_len
// ---------------------------------------------------------------------------
__global__ void k_lengths(const float* __restrict__ mask) {
    int b = blockIdx.x;
    __shared__ int cnt;
    if (threadIdx.x == 0) cnt = 0;
    __syncthreads();
    int local = 0;
    for (int s = threadIdx.x; s < SS; s += blockDim.x)
        if (mask[(size_t)b * SS + s] > -1.0f) local++;
    atomicAdd(&cnt, local);
    __syncthreads();
    if (threadIdx.x == 0) {
        g_len[b] = cnt;
        g_isl[b] = rsqrtf((float)cnt);
    }
}

// ---------------------------------------------------------------------------
// Fused QKV GEMM: C[z][M,N] = X[M,K] * W[z][N,K]^T + bias[z][N]
// TF32 wmma, block 128x128, 4 warps (2x2), warp tile 64x64, BK=16,
// cp.async double-buffered, smem ld=20 (bank-conflict-free fragment rows)
// ---------------------------------------------------------------------------
#define LDS_PAD 20

__device__ __forceinline__ void cp16(void* smem_dst, const void* gsrc) {
    unsigned saddr = (unsigned)__cvta_generic_to_shared(smem_dst);
    asm volatile("cp.async.cg.shared.global [%0], [%1], 16;\n" :: "r"(saddr), "l"(gsrc));
}
__device__ __forceinline__ void cp_commit() {
    asm volatile("cp.async.commit_group;\n");
}
template<int N> __device__ __forceinline__ void cp_wait() {
    asm volatile("cp.async.wait_group %0;\n" :: "n"(N));
}

__global__ __launch_bounds__(128, 2) void k_qkv(
    const float* __restrict__ X,
    const float* __restrict__ Wq, const float* __restrict__ bq,
    const float* __restrict__ Wk, const float* __restrict__ bk,
    const float* __restrict__ Wv, const float* __restrict__ bv,
    float* __restrict__ Cq, float* __restrict__ Ck, float* __restrict__ Cv)
{
    __shared__ float As[2][128 * LDS_PAD];
    __shared__ float Bs[2][128 * LDS_PAD];

    const float* W; const float* bias; float* C;
    if (blockIdx.z == 0)      { W = Wk; bias = bk; C = Ck; }
    else if (blockIdx.z == 1) { W = Wv; bias = bv; C = Cv; }
    else                      { W = Wq; bias = bq; C = Cq; }

    int tid = threadIdx.x;
    int warp = tid >> 5, lane = tid & 31;
    int wm = warp & 1, wn = warp >> 1;
    int m0 = blockIdx.y * 128, n0 = blockIdx.x * 128;

    wmma::fragment<wmma::accumulator, 16, 16, 8, float> acc[4][4];
#pragma unroll
    for (int i = 0; i < 4; i++)
#pragma unroll
        for (int j = 0; j < 4; j++)
            wmma::fill_fragment(acc[i][j], 0.0f);

    // stage loader: 128 rows x 16 floats per matrix = 512 x 16B chunks, 128 thr
    auto load_stage = [&](int st, int k0) {
#pragma unroll
        for (int it = 0; it < 4; it++) {
            int c = tid + it * 128;          // chunk id 0..511
            int row = c >> 2, c4 = c & 3;
            cp16(&As[st][row * LDS_PAD + c4 * 4],
                 &X[(size_t)(m0 + row) * DD + k0 + c4 * 4]);
            cp16(&Bs[st][row * LDS_PAD + c4 * 4],
                 &W[(size_t)(n0 + row) * DD + k0 + c4 * 4]);
        }
        cp_commit();
    };

    load_stage(0, 0);

    const int NK0 = DD / 16;   // 64
    for (int k0i = 0; k0i < NK0; k0i++) {
        int cur = k0i & 1;
        if (k0i + 1 < NK0) {
            load_stage(cur ^ 1, (k0i + 1) * 16);
            cp_wait<1>();
        } else {
            cp_wait<0>();
        }
        __syncthreads();

#pragma unroll
        for (int ksub = 0; ksub < 2; ksub++) {
            wmma::fragment<wmma::matrix_a, 16, 16, 8, wmma::precision::tf32, wmma::row_major> af[4];
            wmma::fragment<wmma::matrix_b, 16, 16, 8, wmma::precision::tf32, wmma::col_major> bf[4];
#pragma unroll
            for (int i = 0; i < 4; i++) {
                wmma::load_matrix_sync(af[i], &As[cur][(wm * 64 + i * 16) * LDS_PAD + ksub * 8], LDS_PAD);
#pragma unroll
                for (int e = 0; e < af[i].num_elements; e++)
                    af[i].x[e] = wmma::__float_to_tf32(af[i].x[e]);
            }
#pragma unroll
            for (int j = 0; j < 4; j++) {
                wmma::load_matrix_sync(bf[j], &Bs[cur][(wn * 64 + j * 16) * LDS_PAD + ksub * 8], LDS_PAD);
#pragma unroll
                for (int e = 0; e < bf[j].num_elements; e++)
                    bf[j].x[e] = wmma::__float_to_tf32(bf[j].x[e]);
            }
#pragma unroll
            for (int i = 0; i < 4; i++)
#pragma unroll
                for (int j = 0; j < 4; j++)
                    wmma::mma_sync(acc[i][j], af[i], bf[j], acc[i][j]);
        }
        __syncthreads();
    }

    // Epilogue: stage per-warp 16x16 in smem, add bias, write
    float* stg = &As[0][0] + warp * 260;
#pragma unroll
    for (int i = 0; i < 4; i++)
#pragma unroll
        for (int j = 0; j < 4; j++) {
            wmma::store_matrix_sync(stg, acc[i][j], 16, wmma::mem_row_major);
            __syncwarp();
            int gr0 = m0 + wm * 64 + i * 16;
            int gc0 = n0 + wn * 64 + j * 16;
#pragma unroll
            for (int e = 0; e < 8; e++) {
                int idx = lane * 8 + e;
                int r = idx >> 4, cc = idx & 15;
                C[(size_t)(gr0 + r) * DD + gc0 + cc] = stg[r * 16 + cc] + bias[gc0 + cc];
            }
            __syncwarp();
        }
}

// ---------------------------------------------------------------------------
// Out[b,k,d] = isl[b] * sum_{s<len[b]} P[s,k] * H[b,s,d]    (TF32 wmma)
// z selects (pk,hk,hkp) vs (pv,hv,hvp)
// ---------------------------------------------------------------------------
__global__ __launch_bounds__(256) void k_proj_tc(
    const float* __restrict__ Pk, const float* __restrict__ Pv,
    const float* __restrict__ Hk, const float* __restrict__ Hv,
    float* __restrict__ Ok, float* __restrict__ Ov)
{
    __shared__ float Acm[16 * 128];  // [ss][m] col-major, ld=128
    __shared__ float Bsm[16 * 128];  // [ss][n] row-major, ld=128
    int tid = threadIdx.x;
    int warp = tid >> 5, lane = tid & 31;
    int wm = warp & 1, wn = warp >> 1;
    int zb = blockIdx.z;
    int b = zb & 7;
    const float* P = (zb < 8) ? Pk : Pv;
    const float* Hsrc = (zb < 8) ? Hk : Hv;
    float* Out = (zb < 8) ? Ok : Ov;
    int m0 = blockIdx.y * 128, n0 = blockIdx.x * 128;
    int len = g_len[b];
    float isl = g_isl[b];
    const float* H = Hsrc + (size_t)b * SS * DD;

    wmma::fragment<wmma::accumulator, 16, 16, 8, float> acc[4][2];
#pragma unroll
    for (int i = 0; i < 4; i++)
#pragma unroll
        for (int j = 0; j < 2; j++)
            wmma::fill_fragment(acc[i][j], 0.0f);

    for (int s0 = 0; s0 < len; s0 += 16) {
#pragma unroll
        for (int it = 0; it < 2; it++) {
            int f4 = tid + it * 256;
            int ss = f4 >> 5, m4 = f4 & 31;
            int s = s0 + ss;
            float4 av;
            if (s < len) av = *(const float4*)&P[(size_t)s * KK + m0 + m4 * 4];
            else         av = make_float4(0.f, 0.f, 0.f, 0.f);
            ((float4*)Acm)[ss * 32 + m4] = av;
            ((float4*)Bsm)[ss * 32 + m4] = *(const float4*)&H[(size_t)s * DD + n0 + m4 * 4];
        }
        __syncthreads();
#pragma unroll
        for (int ksub = 0; ksub < 2; ksub++) {
            wmma::fragment<wmma::matrix_a, 16, 16, 8, wmma::precision::tf32, wmma::col_major> af[4];
            wmma::fragment<wmma::matrix_b, 16, 16, 8, wmma::precision::tf32, wmma::row_major> bf[2];
#pragma unroll
            for (int i = 0; i < 4; i++) {
                wmma::load_matrix_sync(af[i], &Acm[ksub * 8 * 128 + wm * 64 + i * 16], 128);
#pragma unroll
                for (int e = 0; e < af[i].num_elements; e++)
                    af[i].x[e] = wmma::__float_to_tf32(af[i].x[e]);
            }
#pragma unroll
            for (int j = 0; j < 2; j++) {
                wmma::load_matrix_sync(bf[j], &Bsm[ksub * 8 * 128 + wn * 32 + j * 16], 128);
#pragma unroll
                for (int e = 0; e < bf[j].num_elements; e++)
                    bf[j].x[e] = wmma::__float_to_tf32(bf[j].x[e]);
            }
#pragma unroll
            for (int i = 0; i < 4; i++)
#pragma unroll
                for (int j = 0; j < 2; j++)
                    wmma::mma_sync(acc[i][j], af[i], bf[j], acc[i][j]);
        }
        __syncthreads();
    }

    float* stage = Acm + warp * 256;
#pragma unroll
    for (int i = 0; i < 4; i++)
#pragma unroll
        for (int j = 0; j < 2; j++) {
            wmma::store_matrix_sync(stage, acc[i][j], 16, wmma::mem_row_major);
            __syncwarp();
            int gr0 = m0 + wm * 64 + i * 16;
            int gc0 = n0 + wn * 32 + j * 16;
#pragma unroll
            for (int e = 0; e < 8; e++) {
                int idx = lane * 8 + e;
                int r = idx >> 4, c = idx & 15;
                Out[((size_t)b * KK + gr0 + r) * DD + gc0 + c] = stage[r * 16 + c] * isl;
            }
            __syncwarp();
        }
}

// ---------------------------------------------------------------------------
// Fused attention per (b, h, 64-query tile): scores -> softmax -> ctx (fp32)
// ---------------------------------------------------------------------------
__global__ __launch_bounds__(256, 1) void k_attn(
    const float* __restrict__ q, const float* __restrict__ kp,
    const float* __restrict__ vp, float* __restrict__ out)
{
    extern __shared__ float sm[];
    float* ks = sm;                    // 256*64
    float* vs = ks + KK * DH;          // 256*64
    float* qs = vs + KK * DH;          // 64*65
    float* sc = qs + 64 * 65;          // 64*257

    int qt = blockIdx.x, h = blockIdx.y, b = blockIdx.z;
    int s0 = qt * 64;
    int tid = threadIdx.x;

    for (int i = tid; i < KK * 16; i += 256) {
        int kidx = i >> 4, c4 = i & 15;
        size_t off = ((size_t)b * KK + kidx) * DD + h * DH + c4 * 4;
        ((float4*)ks)[i] = *(const float4*)&kp[off];
        ((float4*)vs)[i] = *(const float4*)&vp[off];
    }
    for (int i = tid; i < 64 * 16; i += 256) {
        int r = i >> 4, c4 = i & 15;
        float4 v = *(const float4*)&q[((size_t)b * SS + s0 + r) * DD + h * DH + c4 * 4];
        float* dst = &qs[r * 65 + c4 * 4];
        dst[0] = v.x; dst[1] = v.y; dst[2] = v.z; dst[3] = v.w;
    }
    __syncthreads();

    int qi = tid & 63, grp = tid >> 6;

    // Phase 1: scores
    {
        float qr[64];
#pragma unroll
        for (int d = 0; d < 64; d++) qr[d] = qs[qi * 65 + d];
#pragma unroll 2
        for (int kk = 0; kk < 64; kk++) {
            int k = grp * 64 + kk;
            const float4* krow = (const float4*)&ks[k * DH];
            float a0 = 0.f, a1 = 0.f, a2 = 0.f, a3 = 0.f;
#pragma unroll
            for (int d4 = 0; d4 < 16; d4++) {
                float4 kv = krow[d4];
                a0 += qr[d4 * 4 + 0] * kv.x;
                a1 += qr[d4 * 4 + 1] * kv.y;
                a2 += qr[d4 * 4 + 2] * kv.z;
                a3 += qr[d4 * 4 + 3] * kv.w;
            }
            sc[qi * 257 + k] = (a0 + a1 + a2 + a3) * 0.125f;
        }
    }
    __syncthreads();

    // Phase 2: softmax
    if (tid < 64) {
        float mx = -3.0e38f;
#pragma unroll 4
        for (int k = 0; k < KK; k++) mx = fmaxf(mx, sc[tid * 257 + k]);
        float sum = 0.f;
#pragma unroll 4
        for (int k = 0; k < KK; k++) {
            float e = __expf(sc[tid * 257 + k] - mx);
            sc[tid * 257 + k] = e;
            sum += e;
        }
        float inv = 1.0f / sum;
#pragma unroll 4
        for (int k = 0; k < KK; k++) sc[tid * 257 + k] *= inv;
    }
    __syncthreads();

    // Phase 3: ctx = P @ V
    {
        float o[16];
#pragma unroll
        for (int i = 0; i < 16; i++) o[i] = 0.f;
#pragma unroll 2
        for (int k = 0; k < KK; k++) {
            float p = sc[qi * 257 + k];
            const float4* vrow = (const float4*)&vs[k * DH + grp * 16];
#pragma unroll
            for (int i4 = 0; i4 < 4; i4++) {
                float4 vv = vrow[i4];
                o[i4 * 4 + 0] += p * vv.x;
                o[i4 * 4 + 1] += p * vv.y;
                o[i4 * 4 + 2] += p * vv.z;
                o[i4 * 4 + 3] += p * vv.w;
            }
        }
        float4* op = (float4*)&out[((size_t)b * SS + s0 + qi) * DD + h * DH + grp * 16];
        op[0] = make_float4(o[0],  o[1],  o[2],  o[3]);
        op[1] = make_float4(o[4],  o[5],  o[6],  o[7]);
        op[2] = make_float4(o[8],  o[9],  o[10], o[11]);
        op[3] = make_float4(o[12], o[13], o[14], o[15]);
    }
}

// ---------------------------------------------------------------------------
extern "C" void kernel_launch(void* const* d_in, const int* in_sizes, int n_in,
                              void* d_out, int out_size)
{
    const float* X    = (const float*)d_in[0];
    const float* mask = (const float*)d_in[1];
    const float* Wq   = (const float*)d_in[2];
    const float* bq   = (const float*)d_in[3];
    const float* Wk   = (const float*)d_in[4];
    const float* bk   = (const float*)d_in[5];
    const float* Wv   = (const float*)d_in[6];
    const float* bv   = (const float*)d_in[7];
    const float* pk   = (const float*)d_in[8];
    const float* pv   = (const float*)d_in[9];
    float* out = (float*)d_out;

    float *hk, *hv, *qb, *hkp, *hvp;
    cudaGetSymbolAddress((void**)&hk,  g_hk);
    cudaGetSymbolAddress((void**)&hv,  g_hv);
    cudaGetSymbolAddress((void**)&qb,  g_q);
    cudaGetSymbolAddress((void**)&hkp, g_hkp);
    cudaGetSymbolAddress((void**)&hvp, g_hvp);

    const int ATTN_SMEM = (KK * DH + KK * DH + 64 * 65 + 64 * 257) * 4;
    cudaFuncSetAttribute(k_attn, cudaFuncAttributeMaxDynamicSharedMemorySize, ATTN_SMEM);

    k_lengths<<<BB, 256>>>(mask);

    // fused q/k/v projection GEMMs
    k_qkv<<<dim3(DD / 128, MM / 128, 3), 128>>>(X, Wq, bq, Wk, bk, Wv, bv, qb, hk, hv);

    // fused k/v Linformer projections
    k_proj_tc<<<dim3(DD / 128, KK / 128, 2 * BB), 256>>>(pk, pv, hk, hv, hkp, hvp);

    k_attn<<<dim3(SS / 64, HH, BB), 256, ATTN_SMEM>>>(qb, hkp, hvp, out);
}

// round 5
// speedup vs baseline: 1.4096x; 1.1227x over previous
#include <cuda_runtime.h>
#include <cuda_bf16.h>
#include <mma.h>

using namespace nvcuda;

#define BB 8
#define SS 4096
#define DD 1024
#define HH 16
#define KK 256
#define DH 64
#define MM (BB*SS)

// Scratch (device globals: allocation-free per harness rules)
__device__ float g_hk [(size_t)MM * DD];
__device__ float g_hv [(size_t)MM * DD];
__device__ float g_q  [(size_t)MM * DD];
__device__ float g_hkp[(size_t)BB * KK * DD];
__device__ float g_hvp[(size_t)BB * KK * DD];
__device__ int   g_len[BB];
__device__ float g_isl[BB];

// ---------------------------------------------------------------------------
__global__ void k_lengths(const float* __restrict__ mask) {
    int b = blockIdx.x;
    __shared__ int cnt;
    if (threadIdx.x == 0) cnt = 0;
    __syncthreads();
    int local = 0;
    for (int s = threadIdx.x; s < SS; s += blockDim.x)
        if (mask[(size_t)b * SS + s] > -1.0f) local++;
    atomicAdd(&cnt, local);
    __syncthreads();
    if (threadIdx.x == 0) {
        g_len[b] = cnt;
        g_isl[b] = rsqrtf((float)cnt);
    }
}

// ---------------------------------------------------------------------------
// Fused QKV GEMM (unchanged from R2): TF32 wmma, 128x128 block, 4 warps,
// warp tile 64x64, BK=16, cp.async double-buffered, ld=20 smem
// ---------------------------------------------------------------------------
#define LDS_PAD 20

__device__ __forceinline__ void cp16(void* smem_dst, const void* gsrc) {
    unsigned saddr = (unsigned)__cvta_generic_to_shared(smem_dst);
    asm volatile("cp.async.cg.shared.global [%0], [%1], 16;\n" :: "r"(saddr), "l"(gsrc));
}
__device__ __forceinline__ void cp_commit() {
    asm volatile("cp.async.commit_group;\n");
}
template<int N> __device__ __forceinline__ void cp_wait() {
    asm volatile("cp.async.wait_group %0;\n" :: "n"(N));
}

__global__ __launch_bounds__(128, 2) void k_qkv(
    const float* __restrict__ X,
    const float* __restrict__ Wq, const float* __restrict__ bq,
    const float* __restrict__ Wk, const float* __restrict__ bk,
    const float* __restrict__ Wv, const float* __restrict__ bv,
    float* __restrict__ Cq, float* __restrict__ Ck, float* __restrict__ Cv)
{
    __shared__ float As[2][128 * LDS_PAD];
    __shared__ float Bs[2][128 * LDS_PAD];

    const float* W; const float* bias; float* C;
    if (blockIdx.z == 0)      { W = Wk; bias = bk; C = Ck; }
    else if (blockIdx.z == 1) { W = Wv; bias = bv; C = Cv; }
    else                      { W = Wq; bias = bq; C = Cq; }

    int tid = threadIdx.x;
    int warp = tid >> 5, lane = tid & 31;
    int wm = warp & 1, wn = warp >> 1;
    int m0 = blockIdx.y * 128, n0 = blockIdx.x * 128;

    wmma::fragment<wmma::accumulator, 16, 16, 8, float> acc[4][4];
#pragma unroll
    for (int i = 0; i < 4; i++)
#pragma unroll
        for (int j = 0; j < 4; j++)
            wmma::fill_fragment(acc[i][j], 0.0f);

    auto load_stage = [&](int st, int k0) {
#pragma unroll
        for (int it = 0; it < 4; it++) {
            int c = tid + it * 128;
            int row = c >> 2, c4 = c & 3;
            cp16(&As[st][row * LDS_PAD + c4 * 4],
                 &X[(size_t)(m0 + row) * DD + k0 + c4 * 4]);
            cp16(&Bs[st][row * LDS_PAD + c4 * 4],
                 &W[(size_t)(n0 + row) * DD + k0 + c4 * 4]);
        }
        cp_commit();
    };

    load_stage(0, 0);

    const int NK0 = DD / 16;
    for (int k0i = 0; k0i < NK0; k0i++) {
        int cur = k0i & 1;
        if (k0i + 1 < NK0) {
            load_stage(cur ^ 1, (k0i + 1) * 16);
            cp_wait<1>();
        } else {
            cp_wait<0>();
        }
        __syncthreads();

#pragma unroll
        for (int ksub = 0; ksub < 2; ksub++) {
            wmma::fragment<wmma::matrix_a, 16, 16, 8, wmma::precision::tf32, wmma::row_major> af[4];
            wmma::fragment<wmma::matrix_b, 16, 16, 8, wmma::precision::tf32, wmma::col_major> bf[4];
#pragma unroll
            for (int i = 0; i < 4; i++) {
                wmma::load_matrix_sync(af[i], &As[cur][(wm * 64 + i * 16) * LDS_PAD + ksub * 8], LDS_PAD);
#pragma unroll
                for (int e = 0; e < af[i].num_elements; e++)
                    af[i].x[e] = wmma::__float_to_tf32(af[i].x[e]);
            }
#pragma unroll
            for (int j = 0; j < 4; j++) {
                wmma::load_matrix_sync(bf[j], &Bs[cur][(wn * 64 + j * 16) * LDS_PAD + ksub * 8], LDS_PAD);
#pragma unroll
                for (int e = 0; e < bf[j].num_elements; e++)
                    bf[j].x[e] = wmma::__float_to_tf32(bf[j].x[e]);
            }
#pragma unroll
            for (int i = 0; i < 4; i++)
#pragma unroll
                for (int j = 0; j < 4; j++)
                    wmma::mma_sync(acc[i][j], af[i], bf[j], acc[i][j]);
        }
        __syncthreads();
    }

    float* stg = &As[0][0] + warp * 260;
#pragma unroll
    for (int i = 0; i < 4; i++)
#pragma unroll
        for (int j = 0; j < 4; j++) {
            wmma::store_matrix_sync(stg, acc[i][j], 16, wmma::mem_row_major);
            __syncwarp();
            int gr0 = m0 + wm * 64 + i * 16;
            int gc0 = n0 + wn * 64 + j * 16;
#pragma unroll
            for (int e = 0; e < 8; e++) {
                int idx = lane * 8 + e;
                int r = idx >> 4, cc = idx & 15;
                C[(size_t)(gr0 + r) * DD + gc0 + cc] = stg[r * 16 + cc] + bias[gc0 + cc];
            }
            __syncwarp();
        }
}

// ---------------------------------------------------------------------------
// Out[b,k,d] = isl[b] * sum_{s<len[b]} P[s,k] * H[b,s,d]    (TF32 wmma)
// smem ld = 136 (8-bank row shift, conflict-free fragment loads)
// ---------------------------------------------------------------------------
#define PLD 136

__global__ __launch_bounds__(256) void k_proj_tc(
    const float* __restrict__ Pk, const float* __restrict__ Pv,
    const float* __restrict__ Hk, const float* __restrict__ Hv,
    float* __restrict__ Ok, float* __restrict__ Ov)
{
    __shared__ float Acm[16 * PLD];  // [ss][m] (col-major view for matrix_a)
    __shared__ float Bsm[16 * PLD];  // [ss][n] (row-major view for matrix_b)
    int tid = threadIdx.x;
    int warp = tid >> 5, lane = tid & 31;
    int wm = warp & 1, wn = warp >> 1;
    int zb = blockIdx.z;
    int b = zb & 7;
    const float* P = (zb < 8) ? Pk : Pv;
    const float* Hsrc = (zb < 8) ? Hk : Hv;
    float* Out = (zb < 8) ? Ok : Ov;
    int m0 = blockIdx.y * 128, n0 = blockIdx.x * 128;
    int len = g_len[b];
    float isl = g_isl[b];
    const float* H = Hsrc + (size_t)b * SS * DD;

    wmma::fragment<wmma::accumulator, 16, 16, 8, float> acc[4][2];
#pragma unroll
    for (int i = 0; i < 4; i++)
#pragma unroll
        for (int j = 0; j < 2; j++)
            wmma::fill_fragment(acc[i][j], 0.0f);

    for (int s0 = 0; s0 < len; s0 += 16) {
#pragma unroll
        for (int it = 0; it < 2; it++) {
            int f4 = tid + it * 256;
            int ss = f4 >> 5, m4 = f4 & 31;
            int s = s0 + ss;
            float4 av;
            if (s < len) av = *(const float4*)&P[(size_t)s * KK + m0 + m4 * 4];
            else         av = make_float4(0.f, 0.f, 0.f, 0.f);
            *(float4*)&Acm[ss * PLD + m4 * 4] = av;
            *(float4*)&Bsm[ss * PLD + m4 * 4] = *(const float4*)&H[(size_t)s * DD + n0 + m4 * 4];
        }
        __syncthreads();
#pragma unroll
        for (int ksub = 0; ksub < 2; ksub++) {
            wmma::fragment<wmma::matrix_a, 16, 16, 8, wmma::precision::tf32, wmma::col_major> af[4];
            wmma::fragment<wmma::matrix_b, 16, 16, 8, wmma::precision::tf32, wmma::row_major> bf[2];
#pragma unroll
            for (int i = 0; i < 4; i++) {
                wmma::load_matrix_sync(af[i], &Acm[ksub * 8 * PLD + wm * 64 + i * 16], PLD);
#pragma unroll
                for (int e = 0; e < af[i].num_elements; e++)
                    af[i].x[e] = wmma::__float_to_tf32(af[i].x[e]);
            }
#pragma unroll
            for (int j = 0; j < 2; j++) {
                wmma::load_matrix_sync(bf[j], &Bsm[ksub * 8 * PLD + wn * 32 + j * 16], PLD);
#pragma unroll
                for (int e = 0; e < bf[j].num_elements; e++)
                    bf[j].x[e] = wmma::__float_to_tf32(bf[j].x[e]);
            }
#pragma unroll
            for (int i = 0; i < 4; i++)
#pragma unroll
                for (int j = 0; j < 2; j++)
                    wmma::mma_sync(acc[i][j], af[i], bf[j], acc[i][j]);
        }
        __syncthreads();
    }

    float* stage = Acm + warp * 256;
#pragma unroll
    for (int i = 0; i < 4; i++)
#pragma unroll
        for (int j = 0; j < 2; j++) {
            wmma::store_matrix_sync(stage, acc[i][j], 16, wmma::mem_row_major);
            __syncwarp();
            int gr0 = m0 + wm * 64 + i * 16;
            int gc0 = n0 + wn * 32 + j * 16;
#pragma unroll
            for (int e = 0; e < 8; e++) {
                int idx = lane * 8 + e;
                int r = idx >> 4, c = idx & 15;
                Out[((size_t)b * KK + gr0 + r) * DD + gc0 + c] = stage[r * 16 + c] * isl;
            }
            __syncwarp();
        }
}

// ---------------------------------------------------------------------------
// Tensor-core attention per (b, h, 64-query tile).
// scores(64x256) = Q @ K^T via TF32 wmma (Q fragments straight from gmem),
// fp32 softmax, ctx(64x64) = P @ V via TF32 wmma, stored straight to gmem.
// smem: K[256][72] + V[256][72] + S[64][264] = 210 KB
// ---------------------------------------------------------------------------
#define APAD 72
#define SLD  264

__global__ __launch_bounds__(256, 1) void k_attn_tc(
    const float* __restrict__ q, const float* __restrict__ kp,
    const float* __restrict__ vp, float* __restrict__ out)
{
    extern __shared__ float sm[];
    float* ks = sm;                  // [KK][APAD]
    float* vs = ks + KK * APAD;      // [KK][APAD]
    float* sc = vs + KK * APAD;      // [64][SLD]

    int qt = blockIdx.x, h = blockIdx.y, b = blockIdx.z;
    int s0 = qt * 64;
    int tid = threadIdx.x;
    int warp = tid >> 5;

    // Load K/V tiles: 256 rows x 64 floats each (coalesced float4, padded rows)
    for (int i = tid; i < KK * 16; i += 256) {
        int r = i >> 4, c4 = i & 15;
        size_t off = ((size_t)b * KK + r) * DD + h * DH + c4 * 4;
        *(float4*)&ks[r * APAD + c4 * 4] = *(const float4*)&kp[off];
        *(float4*)&vs[r * APAD + c4 * 4] = *(const float4*)&vp[off];
    }
    __syncthreads();

    // Phase A: scores = Q @ K^T.  Warp w owns score columns [w*32, w*32+32).
    {
        const float* qg = q + ((size_t)b * SS + s0) * DD + h * DH;
        int n0w = warp * 32;
        wmma::fragment<wmma::accumulator, 16, 16, 8, float> accs[4][2];
#pragma unroll
        for (int i = 0; i < 4; i++)
#pragma unroll
            for (int j = 0; j < 2; j++)
                wmma::fill_fragment(accs[i][j], 0.0f);

#pragma unroll
        for (int k8 = 0; k8 < DH / 8; k8++) {
            wmma::fragment<wmma::matrix_a, 16, 16, 8, wmma::precision::tf32, wmma::row_major> af[4];
            wmma::fragment<wmma::matrix_b, 16, 16, 8, wmma::precision::tf32, wmma::col_major> bf[2];
#pragma unroll
            for (int i = 0; i < 4; i++) {
                wmma::load_matrix_sync(af[i], qg + (size_t)(i * 16) * DD + k8 * 8, DD);
#pragma unroll
                for (int e = 0; e < af[i].num_elements; e++)
                    af[i].x[e] = wmma::__float_to_tf32(af[i].x[e]);
            }
#pragma unroll
            for (int j = 0; j < 2; j++) {
                wmma::load_matrix_sync(bf[j], &ks[(n0w + j * 16) * APAD + k8 * 8], APAD);
#pragma unroll
                for (int e = 0; e < bf[j].num_elements; e++)
                    bf[j].x[e] = wmma::__float_to_tf32(bf[j].x[e]);
            }
#pragma unroll
            for (int i = 0; i < 4; i++)
#pragma unroll
                for (int j = 0; j < 2; j++)
                    wmma::mma_sync(accs[i][j], af[i], bf[j], accs[i][j]);
        }
#pragma unroll
        for (int i = 0; i < 4; i++)
#pragma unroll
            for (int j = 0; j < 2; j++)
                wmma::store_matrix_sync(&sc[(i * 16) * SLD + n0w + j * 16],
                                        accs[i][j], SLD, wmma::mem_row_major);
    }
    __syncthreads();

    // Phase B: softmax over K=256 per row (scale 1/sqrt(64) folded in)
    if (tid < 64) {
        float* row = &sc[tid * SLD];
        float mx = -3.0e38f;
#pragma unroll 4
        for (int k = 0; k < KK; k++) mx = fmaxf(mx, row[k]);
        float sum = 0.f;
#pragma unroll 4
        for (int k = 0; k < KK; k++) {
            float e = __expf((row[k] - mx) * 0.125f);
            row[k] = e;
            sum += e;
        }
        float inv = 1.0f / sum;
#pragma unroll 4
        for (int k = 0; k < KK; k++) row[k] *= inv;
    }
    __syncthreads();

    // Phase C: ctx = P @ V.  Warps 2x4: wm in {0,1} (m 32), wn in {0..3} (n 16)
    {
        int wm = warp & 1, wn = warp >> 1;
        wmma::fragment<wmma::accumulator, 16, 16, 8, float> accc[2];
        wmma::fill_fragment(accc[0], 0.0f);
        wmma::fill_fragment(accc[1], 0.0f);

#pragma unroll 4
        for (int k8 = 0; k8 < KK / 8; k8++) {
            wmma::fragment<wmma::matrix_a, 16, 16, 8, wmma::precision::tf32, wmma::row_major> af[2];
            wmma::fragment<wmma::matrix_b, 16, 16, 8, wmma::precision::tf32, wmma::row_major> bf;
#pragma unroll
            for (int i = 0; i < 2; i++) {
                wmma::load_matrix_sync(af[i], &sc[(wm * 32 + i * 16) * SLD + k8 * 8], SLD);
#pragma unroll
                for (int e = 0; e < af[i].num_elements; e++)
                    af[i].x[e] = wmma::__float_to_tf32(af[i].x[e]);
            }
            wmma::load_matrix_sync(bf, &vs[(k8 * 8) * APAD + wn * 16], APAD);
#pragma unroll
            for (int e = 0; e < bf.num_elements; e++)
                bf.x[e] = wmma::__float_to_tf32(bf.x[e]);
#pragma unroll
            for (int i = 0; i < 2; i++)
                wmma::mma_sync(accc[i], af[i], bf, accc[i]);
        }

#pragma unroll
        for (int i = 0; i < 2; i++) {
            float* dst = out + ((size_t)b * SS + s0 + wm * 32 + i * 16) * DD + h * DH + wn * 16;
            wmma::store_matrix_sync(dst, accc[i], DD, wmma::mem_row_major);
        }
    }
}

// ---------------------------------------------------------------------------
extern "C" void kernel_launch(void* const* d_in, const int* in_sizes, int n_in,
                              void* d_out, int out_size)
{
    const float* X    = (const float*)d_in[0];
    const float* mask = (const float*)d_in[1];
    const float* Wq   = (const float*)d_in[2];
    const float* bq   = (const float*)d_in[3];
    const float* Wk   = (const float*)d_in[4];
    const float* bk   = (const float*)d_in[5];
    const float* Wv   = (const float*)d_in[6];
    const float* bv   = (const float*)d_in[7];
    const float* pk   = (const float*)d_in[8];
    const float* pv   = (const float*)d_in[9];
    float* out = (float*)d_out;

    float *hk, *hv, *qb, *hkp, *hvp;
    cudaGetSymbolAddress((void**)&hk,  g_hk);
    cudaGetSymbolAddress((void**)&hv,  g_hv);
    cudaGetSymbolAddress((void**)&qb,  g_q);
    cudaGetSymbolAddress((void**)&hkp, g_hkp);
    cudaGetSymbolAddress((void**)&hvp, g_hvp);

    const int ATTN_SMEM = (2 * KK * APAD + 64 * SLD) * 4;   // 210 KB
    cudaFuncSetAttribute(k_attn_tc, cudaFuncAttributeMaxDynamicSharedMemorySize, ATTN_SMEM);

    k_lengths<<<BB, 256>>>(mask);

    k_qkv<<<dim3(DD / 128, MM / 128, 3), 128>>>(X, Wq, bq, Wk, bk, Wv, bv, qb, hk, hv);

    k_proj_tc<<<dim3(DD / 128, KK / 128, 2 * BB), 256>>>(pk, pv, hk, hv, hkp, hvp);

    k_attn_tc<<<dim3(SS / 64, HH, BB), 256, ATTN_SMEM>>>(qb, hkp, hvp, out);
}

// round 7
// speedup vs baseline: 2.1198x; 1.5038x over previous
#include <cuda_runtime.h>
#include <cuda_bf16.h>
#include <mma.h>

using namespace nvcuda;

#define BB 8
#define SS 4096
#define DD 1024
#define HH 16
#define KK 256
#define DH 64
#define MM (BB*SS)

// Scratch (device globals: allocation-free per harness rules)
__device__ float g_q  [(size_t)MM * DD];           // Q projection
__device__ float g_yk [(size_t)BB * KK * DD];      // P_k'^T @ X  (scaled by isl)
__device__ float g_yv [(size_t)BB * KK * DD];      // P_v'^T @ X
__device__ float g_hkp[(size_t)BB * KK * DD];      // final projected K
__device__ float g_hvp[(size_t)BB * KK * DD];      // final projected V
__device__ float g_colsum[2 * BB * KK];            // isl * sum_s m*P[s,k]
__device__ int   g_len[BB];
__device__ float g_isl[BB];

// ---------------------------------------------------------------------------
__global__ void k_lengths(const float* __restrict__ mask) {
    int b = blockIdx.x;
    __shared__ int cnt;
    if (threadIdx.x == 0) cnt = 0;
    __syncthreads();
    int local = 0;
    for (int s = threadIdx.x; s < SS; s += blockDim.x)
        if (mask[(size_t)b * SS + s] > -1.0f) local++;
    atomicAdd(&cnt, local);
    __syncthreads();
    if (threadIdx.x == 0) {
        g_len[b] = cnt;
        g_isl[b] = rsqrtf((float)cnt);
    }
}

// colsum[z][b][kc] = isl[b] * sum_{s<len[b]} P_z[s][kc]
__global__ void k_colsum(const float* __restrict__ Pk, const float* __restrict__ Pv) {
    int z = blockIdx.x, b = blockIdx.y;
    int kc = threadIdx.x;                 // 256 threads == KK
    const float* P = z ? Pv : Pk;
    int len = g_len[b];
    float s = 0.f;
    for (int i = 0; i < len; i++) s += P[(size_t)i * KK + kc];
    g_colsum[(z * BB + b) * KK + kc] = s * g_isl[b];
}

// ---------------------------------------------------------------------------
// cp.async helpers
// ---------------------------------------------------------------------------
__device__ __forceinline__ void cp16(void* smem_dst, const void* gsrc) {
    unsigned saddr = (unsigned)__cvta_generic_to_shared(smem_dst);
    asm volatile("cp.async.cg.shared.global [%0], [%1], 16;\n" :: "r"(saddr), "l"(gsrc));
}
// predicated: zero-fills destination when !valid (src not dereferenced meaningfully)
__device__ __forceinline__ void cp16p(void* smem_dst, const void* gsrc, bool valid) {
    unsigned saddr = (unsigned)__cvta_generic_to_shared(smem_dst);
    int sz = valid ? 16 : 0;
    asm volatile("cp.async.cg.shared.global [%0], [%1], 16, %2;\n"
                 :: "r"(saddr), "l"(gsrc), "r"(sz));
}
__device__ __forceinline__ void cp_commit() {
    asm volatile("cp.async.commit_group;\n");
}
template<int N> __device__ __forceinline__ void cp_wait() {
    asm volatile("cp.async.wait_group %0;\n" :: "n"(N));
}

// ---------------------------------------------------------------------------
// Q GEMM: C[M,N] = X[M,K] * Wq[N,K]^T + bq[N]
// TF32 wmma, 128x128 block, 4 warps, warp tile 64x64, BK=16, cp.async 2-stage
// ---------------------------------------------------------------------------
#define LDS_PAD 20

__global__ __launch_bounds__(128, 2) void k_qgemm(
    const float* __restrict__ X,
    const float* __restrict__ Wq, const float* __restrict__ bq,
    float* __restrict__ Cq)
{
    __shared__ float As[2][128 * LDS_PAD];
    __shared__ float Bs[2][128 * LDS_PAD];

    int tid = threadIdx.x;
    int warp = tid >> 5, lane = tid & 31;
    int wm = warp & 1, wn = warp >> 1;
    int m0 = blockIdx.y * 128, n0 = blockIdx.x * 128;

    wmma::fragment<wmma::accumulator, 16, 16, 8, float> acc[4][4];
#pragma unroll
    for (int i = 0; i < 4; i++)
#pragma unroll
        for (int j = 0; j < 4; j++)
            wmma::fill_fragment(acc[i][j], 0.0f);

    auto load_stage = [&](int st, int k0) {
#pragma unroll
        for (int it = 0; it < 4; it++) {
            int c = tid + it * 128;
            int row = c >> 2, c4 = c & 3;
            cp16(&As[st][row * LDS_PAD + c4 * 4],
                 &X[(size_t)(m0 + row) * DD + k0 + c4 * 4]);
            cp16(&Bs[st][row * LDS_PAD + c4 * 4],
                 &Wq[(size_t)(n0 + row) * DD + k0 + c4 * 4]);
        }
        cp_commit();
    };

    load_stage(0, 0);

    const int NK0 = DD / 16;
    for (int k0i = 0; k0i < NK0; k0i++) {
        int cur = k0i & 1;
        if (k0i + 1 < NK0) {
            load_stage(cur ^ 1, (k0i + 1) * 16);
            cp_wait<1>();
        } else {
            cp_wait<0>();
        }
        __syncthreads();

#pragma unroll
        for (int ksub = 0; ksub < 2; ksub++) {
            wmma::fragment<wmma::matrix_a, 16, 16, 8, wmma::precision::tf32, wmma::row_major> af[4];
            wmma::fragment<wmma::matrix_b, 16, 16, 8, wmma::precision::tf32, wmma::col_major> bf[4];
#pragma unroll
            for (int i = 0; i < 4; i++) {
                wmma::load_matrix_sync(af[i], &As[cur][(wm * 64 + i * 16) * LDS_PAD + ksub * 8], LDS_PAD);
#pragma unroll
                for (int e = 0; e < af[i].num_elements; e++)
                    af[i].x[e] = wmma::__float_to_tf32(af[i].x[e]);
            }
#pragma unroll
            for (int j = 0; j < 4; j++) {
                wmma::load_matrix_sync(bf[j], &Bs[cur][(wn * 64 + j * 16) * LDS_PAD + ksub * 8], LDS_PAD);
#pragma unroll
                for (int e = 0; e < bf[j].num_elements; e++)
                    bf[j].x[e] = wmma::__float_to_tf32(bf[j].x[e]);
            }
#pragma unroll
            for (int i = 0; i < 4; i++)
#pragma unroll
                for (int j = 0; j < 4; j++)
                    wmma::mma_sync(acc[i][j], af[i], bf[j], acc[i][j]);
        }
        __syncthreads();
    }

    float* stg = &As[0][0] + warp * 260;
#pragma unroll
    for (int i = 0; i < 4; i++)
#pragma unroll
        for (int j = 0; j < 4; j++) {
            wmma::store_matrix_sync(stg, acc[i][j], 16, wmma::mem_row_major);
            __syncwarp();
            int gr0 = m0 + wm * 64 + i * 16;
            int gc0 = n0 + wn * 64 + j * 16;
#pragma unroll
            for (int e = 0; e < 8; e++) {
                int idx = lane * 8 + e;
                int r = idx >> 4, cc = idx & 15;
                Cq[(size_t)(gr0 + r) * DD + gc0 + cc] = stg[r * 16 + cc] + bq[gc0 + cc];
            }
            __syncwarp();
        }
}

// ---------------------------------------------------------------------------
// Masked projection of X:  Y_z[b][kc][d] = isl[b] * sum_{s<len} P_z[s][kc] * X[b][s][d]
// M=256 (all of K-dim), N=128 per block, BK=16, cp.async double-buffered.
// 8 warps (4m x 2n), warp tile 64x64.
// ---------------------------------------------------------------------------
#define AP 264   // A stage ld (16 x 256 tile), 264 % 32 == 8 -> conflict-free
#define BP 136   // B stage ld (16 x 128 tile)

__global__ __launch_bounds__(256) void k_projX(
    const float* __restrict__ Pk, const float* __restrict__ Pv,
    const float* __restrict__ X,
    float* __restrict__ Yk, float* __restrict__ Yv)
{
    __shared__ float As[2][16 * AP];
    __shared__ float Bs[2][16 * BP];

    int zb = blockIdx.z;
    int z = zb >> 3, b = zb & 7;
    const float* P = z ? Pv : Pk;
    float* Y = (z ? Yv : Yk) + (size_t)b * KK * DD;
    const float* Xb = X + (size_t)b * SS * DD;
    int n0 = blockIdx.x * 128;
    int len = g_len[b];
    float isl = g_isl[b];

    int tid = threadIdx.x;
    int warp = tid >> 5;
    int wm = warp & 3, wn = warp >> 2;   // 4 m-warps x 2 n-warps

    wmma::fragment<wmma::accumulator, 16, 16, 8, float> acc[4][4];
#pragma unroll
    for (int i = 0; i < 4; i++)
#pragma unroll
        for (int j = 0; j < 4; j++)
            wmma::fill_fragment(acc[i][j], 0.0f);

    auto load_stage = [&](int st, int s0) {
        // A: P[s0:s0+16, 0:256] -> As[ss][m], zero rows with s >= len
#pragma unroll
        for (int it = 0; it < 4; it++) {
            int f4 = tid + it * 256;          // 0..1023
            int ss = f4 >> 6, c4 = f4 & 63;
            int s = s0 + ss;
            cp16p(&As[st][ss * AP + c4 * 4], &P[(size_t)s * KK + c4 * 4], s < len);
        }
        // B: X[b][s0:s0+16, n0:n0+128] -> Bs[ss][n]
#pragma unroll
        for (int it = 0; it < 2; it++) {
            int f4 = tid + it * 256;          // 0..511
            int ss = f4 >> 5, c4 = f4 & 31;
            int s = s0 + ss;
            cp16p(&Bs[st][ss * BP + c4 * 4], &Xb[(size_t)s * DD + n0 + c4 * 4], s < len);
        }
        cp_commit();
    };

    int nsteps = (len + 15) >> 4;
    load_stage(0, 0);

    for (int st = 0; st < nsteps; st++) {
        int cur = st & 1;
        if (st + 1 < nsteps) {
            load_stage(cur ^ 1, (st + 1) * 16);
            cp_wait<1>();
        } else {
            cp_wait<0>();
        }
        __syncthreads();

#pragma unroll
        for (int ksub = 0; ksub < 2; ksub++) {
            wmma::fragment<wmma::matrix_a, 16, 16, 8, wmma::precision::tf32, wmma::col_major> af[4];
            wmma::fragment<wmma::matrix_b, 16, 16, 8, wmma::precision::tf32, wmma::row_major> bf[4];
#pragma unroll
            for (int i = 0; i < 4; i++) {
                wmma::load_matrix_sync(af[i], &As[cur][ksub * 8 * AP + wm * 64 + i * 16], AP);
#pragma unroll
                for (int e = 0; e < af[i].num_elements; e++)
                    af[i].x[e] = wmma::__float_to_tf32(af[i].x[e]);
            }
#pragma unroll
            for (int j = 0; j < 4; j++) {
                wmma::load_matrix_sync(bf[j], &Bs[cur][ksub * 8 * BP + wn * 64 + j * 16], BP);
#pragma unroll
                for (int e = 0; e < bf[j].num_elements; e++)
                    bf[j].x[e] = wmma::__float_to_tf32(bf[j].x[e]);
            }
#pragma unroll
            for (int i = 0; i < 4; i++)
#pragma unroll
                for (int j = 0; j < 4; j++)
                    wmma::mma_sync(acc[i][j], af[i], bf[j], acc[i][j]);
        }
        __syncthreads();
    }

    // Epilogue: scale by isl, store straight to gmem (Y is scratch)
#pragma unroll
    for (int i = 0; i < 4; i++)
#pragma unroll
        for (int j = 0; j < 4; j++) {
#pragma unroll
            for (int e = 0; e < acc[i][j].num_elements; e++)
                acc[i][j].x[e] *= isl;
            int gr = wm * 64 + i * 16;
            int gc = n0 + wn * 64 + j * 16;
            wmma::store_matrix_sync(&Y[(size_t)gr * DD + gc], acc[i][j], DD, wmma::mem_row_major);
        }
}

// ---------------------------------------------------------------------------
// Small GEMM: O_z[b] = Y_z[b] @ W_z^T + colsum_z[b] (x) bias_z
// M=256, N=1024, K=1024.  Same structure as k_qgemm.
// ---------------------------------------------------------------------------
__global__ __launch_bounds__(128, 2) void k_gemm2(
    const float* __restrict__ Yk, const float* __restrict__ Yv,
    const float* __restrict__ Wk, const float* __restrict__ bk,
    const float* __restrict__ Wv, const float* __restrict__ bv,
    float* __restrict__ Ok, float* __restrict__ Ov)
{
    __shared__ float As[2][128 * LDS_PAD];
    __shared__ float Bs[2][128 * LDS_PAD];

    int zb = blockIdx.z;
    int z = zb >> 3, b = zb & 7;
    const float* A = (z ? Yv : Yk) + (size_t)b * KK * DD;
    const float* W = z ? Wv : Wk;
    const float* bias = z ? bv : bk;
    float* C = (z ? Ov : Ok) + (size_t)b * KK * DD;
    const float* cs = g_colsum + (z * BB + b) * KK;

    int tid = threadIdx.x;
    int warp = tid >> 5, lane = tid & 31;
    int wm = warp & 1, wn = warp >> 1;
    int m0 = blockIdx.y * 128, n0 = blockIdx.x * 128;

    wmma::fragment<wmma::accumulator, 16, 16, 8, float> acc[4][4];
#pragma unroll
    for (int i = 0; i < 4; i++)
#pragma unroll
        for (int j = 0; j < 4; j++)
            wmma::fill_fragment(acc[i][j], 0.0f);

    auto load_stage = [&](int st, int k0) {
#pragma unroll
        for (int it = 0; it < 4; it++) {
            int c = tid + it * 128;
            int row = c >> 2, c4 = c & 3;
            cp16(&As[st][row * LDS_PAD + c4 * 4],
                 &A[(size_t)(m0 + row) * DD + k0 + c4 * 4]);
            cp16(&Bs[st][row * LDS_PAD + c4 * 4],
                 &W[(size_t)(n0 + row) * DD + k0 + c4 * 4]);
        }
        cp_commit();
    };

    load_stage(0, 0);

    const int NK0 = DD / 16;
    for (int k0i = 0; k0i < NK0; k0i++) {
        int cur = k0i & 1;
        if (k0i + 1 < NK0) {
            load_stage(cur ^ 1, (k0i + 1) * 16);
            cp_wait<1>();
        } else {
            cp_wait<0>();
        }
        __syncthreads();

#pragma unroll
        for (int ksub = 0; ksub < 2; ksub++) {
            wmma::fragment<wmma::matrix_a, 16, 16, 8, wmma::precision::tf32, wmma::row_major> af[4];
            wmma::fragment<wmma::matrix_b, 16, 16, 8, wmma::precision::tf32, wmma::col_major> bf[4];
#pragma unroll
            for (int i = 0; i < 4; i++) {
                wmma::load_matrix_sync(af[i], &As[cur][(wm * 64 + i * 16) * LDS_PAD + ksub * 8], LDS_PAD);
#pragma unroll
                for (int e = 0; e < af[i].num_elements; e++)
                    af[i].x[e] = wmma::__float_to_tf32(af[i].x[e]);
            }
#pragma unroll
            for (int j = 0; j < 4; j++) {
                wmma::load_matrix_sync(bf[j], &Bs[cur][(wn * 64 + j * 16) * LDS_PAD + ksub * 8], LDS_PAD);
#pragma unroll
                for (int e = 0; e < bf[j].num_elements; e++)
                    bf[j].x[e] = wmma::__float_to_tf32(bf[j].x[e]);
            }
#pragma unroll
            for (int i = 0; i < 4; i++)
#pragma unroll
                for (int j = 0; j < 4; j++)
                    wmma::mma_sync(acc[i][j], af[i], bf[j], acc[i][j]);
        }
        __syncthreads();
    }

    float* stg = &As[0][0] + warp * 260;
#pragma unroll
    for (int i = 0; i < 4; i++)
#pragma unroll
        for (int j = 0; j < 4; j++) {
            wmma::store_matrix_sync(stg, acc[i][j], 16, wmma::mem_row_major);
            __syncwarp();
            int gr0 = m0 + wm * 64 + i * 16;
            int gc0 = n0 + wn * 64 + j * 16;
#pragma unroll
            for (int e = 0; e < 8; e++) {
                int idx = lane * 8 + e;
                int r = idx >> 4, cc = idx & 15;
                C[(size_t)(gr0 + r) * DD + gc0 + cc] =
                    stg[r * 16 + cc] + cs[gr0 + r] * bias[gc0 + cc];
            }
            __syncwarp();
        }
}

// ---------------------------------------------------------------------------
// Tensor-core attention per (b, h, 64-query tile). Unchanged from R5.
// ---------------------------------------------------------------------------
#define APAD 72
#define SLD  264

__global__ __launch_bounds__(256, 1) void k_attn_tc(
    const float* __restrict__ q, const float* __restrict__ kp,
    const float* __restrict__ vp, float* __restrict__ out)
{
    extern __shared__ float sm[];
    float* ks = sm;                  // [KK][APAD]
    float* vs = ks + KK * APAD;      // [KK][APAD]
    float* sc = vs + KK * APAD;      // [64][SLD]

    int qt = blockIdx.x, h = blockIdx.y, b = blockIdx.z;
    int s0 = qt * 64;
    int tid = threadIdx.x;
    int warp = tid >> 5;

    for (int i = tid; i < KK * 16; i += 256) {
        int r = i >> 4, c4 = i & 15;
        size_t off = ((size_t)b * KK + r) * DD + h * DH + c4 * 4;
        *(float4*)&ks[r * APAD + c4 * 4] = *(const float4*)&kp[off];
        *(float4*)&vs[r * APAD + c4 * 4] = *(const float4*)&vp[off];
    }
    __syncthreads();

    // Phase A: scores = Q @ K^T
    {
        const float* qg = q + ((size_t)b * SS + s0) * DD + h * DH;
        int n0w = warp * 32;
        wmma::fragment<wmma::accumulator, 16, 16, 8, float> accs[4][2];
#pragma unroll
        for (int i = 0; i < 4; i++)
#pragma unroll
            for (int j = 0; j < 2; j++)
                wmma::fill_fragment(accs[i][j], 0.0f);

#pragma unroll
        for (int k8 = 0; k8 < DH / 8; k8++) {
            wmma::fragment<wmma::matrix_a, 16, 16, 8, wmma::precision::tf32, wmma::row_major> af[4];
            wmma::fragment<wmma::matrix_b, 16, 16, 8, wmma::precision::tf32, wmma::col_major> bf[2];
#pragma unroll
            for (int i = 0; i < 4; i++) {
                wmma::load_matrix_sync(af[i], qg + (size_t)(i * 16) * DD + k8 * 8, DD);
#pragma unroll
                for (int e = 0; e < af[i].num_elements; e++)
                    af[i].x[e] = wmma::__float_to_tf32(af[i].x[e]);
            }
#pragma unroll
            for (int j = 0; j < 2; j++) {
                wmma::load_matrix_sync(bf[j], &ks[(n0w + j * 16) * APAD + k8 * 8], APAD);
#pragma unroll
                for (int e = 0; e < bf[j].num_elements; e++)
                    bf[j].x[e] = wmma::__float_to_tf32(bf[j].x[e]);
            }
#pragma unroll
            for (int i = 0; i < 4; i++)
#pragma unroll
                for (int j = 0; j < 2; j++)
                    wmma::mma_sync(accs[i][j], af[i], bf[j], accs[i][j]);
        }
#pragma unroll
        for (int i = 0; i < 4; i++)
#pragma unroll
            for (int j = 0; j < 2; j++)
                wmma::store_matrix_sync(&sc[(i * 16) * SLD + n0w + j * 16],
                                        accs[i][j], SLD, wmma::mem_row_major);
    }
    __syncthreads();

    // Phase B: softmax (scale folded in)
    if (tid < 64) {
        float* row = &sc[tid * SLD];
        float mx = -3.0e38f;
#pragma unroll 4
        for (int k = 0; k < KK; k++) mx = fmaxf(mx, row[k]);
        float sum = 0.f;
#pragma unroll 4
        for (int k = 0; k < KK; k++) {
            float e = __expf((row[k] - mx) * 0.125f);
            row[k] = e;
            sum += e;
        }
        float inv = 1.0f / sum;
#pragma unroll 4
        for (int k = 0; k < KK; k++) row[k] *= inv;
    }
    __syncthreads();

    // Phase C: ctx = P @ V
    {
        int wm = warp & 1, wn = warp >> 1;
        wmma::fragment<wmma::accumulator, 16, 16, 8, float> accc[2];
        wmma::fill_fragment(accc[0], 0.0f);
        wmma::fill_fragment(accc[1], 0.0f);

#pragma unroll 4
        for (int k8 = 0; k8 < KK / 8; k8++) {
            wmma::fragment<wmma::matrix_a, 16, 16, 8, wmma::precision::tf32, wmma::row_major> af[2];
            wmma::fragment<wmma::matrix_b, 16, 16, 8, wmma::precision::tf32, wmma::row_major> bf;
#pragma unroll
            for (int i = 0; i < 2; i++) {
                wmma::load_matrix_sync(af[i], &sc[(wm * 32 + i * 16) * SLD + k8 * 8], SLD);
#pragma unroll
                for (int e = 0; e < af[i].num_elements; e++)
                    af[i].x[e] = wmma::__float_to_tf32(af[i].x[e]);
            }
            wmma::load_matrix_sync(bf, &vs[(k8 * 8) * APAD + wn * 16], APAD);
#pragma unroll
            for (int e = 0; e < bf.num_elements; e++)
                bf.x[e] = wmma::__float_to_tf32(bf.x[e]);
#pragma unroll
            for (int i = 0; i < 2; i++)
                wmma::mma_sync(accc[i], af[i], bf, accc[i]);
        }

#pragma unroll
        for (int i = 0; i < 2; i++) {
            float* dst = out + ((size_t)b * SS + s0 + wm * 32 + i * 16) * DD + h * DH + wn * 16;
            wmma::store_matrix_sync(dst, accc[i], DD, wmma::mem_row_major);
        }
    }
}

// ---------------------------------------------------------------------------
extern "C" void kernel_launch(void* const* d_in, const int* in_sizes, int n_in,
                              void* d_out, int out_size)
{
    const float* X    = (const float*)d_in[0];
    const float* mask = (const float*)d_in[1];
    const float* Wq   = (const float*)d_in[2];
    const float* bq   = (const float*)d_in[3];
    const float* Wk   = (const float*)d_in[4];
    const float* bk   = (const float*)d_in[5];
    const float* Wv   = (const float*)d_in[6];
    const float* bv   = (const float*)d_in[7];
    const float* pk   = (const float*)d_in[8];
    const float* pv   = (const float*)d_in[9];
    float* out = (float*)d_out;

    float *qb, *yk, *yv, *hkp, *hvp;
    cudaGetSymbolAddress((void**)&qb,  g_q);
    cudaGetSymbolAddress((void**)&yk,  g_yk);
    cudaGetSymbolAddress((void**)&yv,  g_yv);
    cudaGetSymbolAddress((void**)&hkp, g_hkp);
    cudaGetSymbolAddress((void**)&hvp, g_hvp);

    const int ATTN_SMEM = (2 * KK * APAD + 64 * SLD) * 4;   // 210 KB
    cudaFuncSetAttribute(k_attn_tc, cudaFuncAttributeMaxDynamicSharedMemorySize, ATTN_SMEM);

    k_lengths<<<BB, 256>>>(mask);
    k_colsum<<<dim3(2, BB), KK>>>(pk, pv);

    // Y_z = isl * P_z'^T @ X   (masked projection of X directly)
    k_projX<<<dim3(DD / 128, 1, 16), 256>>>(pk, pv, X, yk, yv);

    // hkp/hvp = Y_z @ W_z^T + colsum (x) bias
    k_gemm2<<<dim3(DD / 128, KK / 128, 16), 128>>>(yk, yv, Wk, bk, Wv, bv, hkp, hvp);

    // Q projection
    k_qgemm<<<dim3(DD / 128, MM / 128), 128>>>(X, Wq, bq, qb);

    k_attn_tc<<<dim3(SS / 64, HH, BB), 256, ATTN_SMEM>>>(qb, hkp, hvp, out);
}

// round 8
// speedup vs baseline: 3.4358x; 1.6208x over previous
#include <cuda_runtime.h>
#include <cuda_fp16.h>
#include <mma.h>

using namespace nvcuda;

#define BB 8
#define SS 4096
#define DD 1024
#define HH 16
#define KK 256
#define DH 64
#define MM (BB*SS)

// Scratch (device globals)
__device__ __half g_Xh [(size_t)MM * DD];          // X in half
__device__ __half g_Wqh[(size_t)DD * DD];
__device__ __half g_Wkh[(size_t)DD * DD];
__device__ __half g_Wvh[(size_t)DD * DD];
__device__ __half g_Pkh[(size_t)SS * KK];
__device__ __half g_Pvh[(size_t)SS * KK];
__device__ __half g_qh [(size_t)MM * DD];          // Q projection (half)
__device__ __half g_yk [(size_t)BB * KK * DD];     // isl * Pk'^T @ X
__device__ __half g_yv [(size_t)BB * KK * DD];
__device__ __half g_hkp[(size_t)BB * KK * DD];     // projected K (half)
__device__ __half g_hvp[(size_t)BB * KK * DD];     // projected V (half)
__device__ float  g_colsum[2 * BB * KK];
__device__ int    g_len[BB];
__device__ float  g_isl[BB];

// ---------------------------------------------------------------------------
__global__ void k_lengths(const float* __restrict__ mask) {
    int b = blockIdx.x;
    __shared__ int cnt;
    if (threadIdx.x == 0) cnt = 0;
    __syncthreads();
    int local = 0;
    for (int s = threadIdx.x; s < SS; s += blockDim.x)
        if (mask[(size_t)b * SS + s] > -1.0f) local++;
    atomicAdd(&cnt, local);
    __syncthreads();
    if (threadIdx.x == 0) {
        g_len[b] = cnt;
        g_isl[b] = rsqrtf((float)cnt);
    }
}

__global__ void k_colsum(const float* __restrict__ Pk, const float* __restrict__ Pv) {
    int z = blockIdx.x, b = blockIdx.y;
    int kc = threadIdx.x;
    const float* P = z ? Pv : Pk;
    int len = g_len[b];
    float s = 0.f;
    for (int i = 0; i < len; i++) s += P[(size_t)i * KK + kc];
    g_colsum[(z * BB + b) * KK + kc] = s * g_isl[b];
}

// fp32 -> fp16 elementwise (n divisible by 8)
__global__ void k_f2h(const float* __restrict__ s, __half* __restrict__ d, size_t n) {
    size_t i = ((size_t)blockIdx.x * blockDim.x + threadIdx.x) * 8;
    if (i >= n) return;
    float4 a = *(const float4*)&s[i];
    float4 b = *(const float4*)&s[i + 4];
    __half2* dp = (__half2*)&d[i];
    dp[0] = __floats2half2_rn(a.x, a.y);
    dp[1] = __floats2half2_rn(a.z, a.w);
    dp[2] = __floats2half2_rn(b.x, b.y);
    dp[3] = __floats2half2_rn(b.z, b.w);
}

// ---------------------------------------------------------------------------
// cp.async helpers
// ---------------------------------------------------------------------------
__device__ __forceinline__ void cp16(void* smem_dst, const void* gsrc) {
    unsigned saddr = (unsigned)__cvta_generic_to_shared(smem_dst);
    asm volatile("cp.async.cg.shared.global [%0], [%1], 16;\n" :: "r"(saddr), "l"(gsrc));
}
__device__ __forceinline__ void cp16p(void* smem_dst, const void* gsrc, bool valid) {
    unsigned saddr = (unsigned)__cvta_generic_to_shared(smem_dst);
    int sz = valid ? 16 : 0;
    asm volatile("cp.async.cg.shared.global [%0], [%1], 16, %2;\n"
                 :: "r"(saddr), "l"(gsrc), "r"(sz));
}
__device__ __forceinline__ void cp_commit() {
    asm volatile("cp.async.commit_group;\n");
}
template<int N> __device__ __forceinline__ void cp_wait() {
    asm volatile("cp.async.wait_group %0;\n" :: "n"(N));
}

// ---------------------------------------------------------------------------
// Q GEMM (half): C[M,N] = Xh * Wqh^T + bq, output half.
// 128x128 block, 4 warps, warp 64x64, BK=32 halves, 2-stage cp.async
// ---------------------------------------------------------------------------
#define HLD 40   // 32 + 8 halves pad

__global__ __launch_bounds__(128, 2) void k_qgemm_h(
    const __half* __restrict__ X, const __half* __restrict__ W,
    const float* __restrict__ bias, __half* __restrict__ C)
{
    __shared__ __half As[2][128 * HLD];
    __shared__ __half Bs[2][128 * HLD];
    __shared__ float  stgF[4 * 256];

    int tid = threadIdx.x;
    int warp = tid >> 5, lane = tid & 31;
    int wm = warp & 1, wn = warp >> 1;
    int m0 = blockIdx.y * 128, n0 = blockIdx.x * 128;

    wmma::fragment<wmma::accumulator, 16, 16, 16, float> acc[4][4];
#pragma unroll
    for (int i = 0; i < 4; i++)
#pragma unroll
        for (int j = 0; j < 4; j++)
            wmma::fill_fragment(acc[i][j], 0.0f);

    auto load_stage = [&](int st, int k0) {
#pragma unroll
        for (int it = 0; it < 4; it++) {
            int c = tid + it * 128;           // 512 chunks of 8 halves
            int row = c >> 2, c8 = c & 3;
            cp16(&As[st][row * HLD + c8 * 8], &X[(size_t)(m0 + row) * DD + k0 + c8 * 8]);
            cp16(&Bs[st][row * HLD + c8 * 8], &W[(size_t)(n0 + row) * DD + k0 + c8 * 8]);
        }
        cp_commit();
    };

    load_stage(0, 0);
    const int NK0 = DD / 32;
    for (int k0i = 0; k0i < NK0; k0i++) {
        int cur = k0i & 1;
        if (k0i + 1 < NK0) { load_stage(cur ^ 1, (k0i + 1) * 32); cp_wait<1>(); }
        else               { cp_wait<0>(); }
        __syncthreads();

#pragma unroll
        for (int ksub = 0; ksub < 2; ksub++) {
            wmma::fragment<wmma::matrix_a, 16, 16, 16, __half, wmma::row_major> af[4];
            wmma::fragment<wmma::matrix_b, 16, 16, 16, __half, wmma::col_major> bf[4];
#pragma unroll
            for (int i = 0; i < 4; i++)
                wmma::load_matrix_sync(af[i], &As[cur][(wm * 64 + i * 16) * HLD + ksub * 16], HLD);
#pragma unroll
            for (int j = 0; j < 4; j++)
                wmma::load_matrix_sync(bf[j], &Bs[cur][(wn * 64 + j * 16) * HLD + ksub * 16], HLD);
#pragma unroll
            for (int i = 0; i < 4; i++)
#pragma unroll
                for (int j = 0; j < 4; j++)
                    wmma::mma_sync(acc[i][j], af[i], bf[j], acc[i][j]);
        }
        __syncthreads();
    }

    float* stg = stgF + warp * 256;
#pragma unroll
    for (int i = 0; i < 4; i++)
#pragma unroll
        for (int j = 0; j < 4; j++) {
            wmma::store_matrix_sync(stg, acc[i][j], 16, wmma::mem_row_major);
            __syncwarp();
            int gr0 = m0 + wm * 64 + i * 16;
            int gc0 = n0 + wn * 64 + j * 16;
#pragma unroll
            for (int e = 0; e < 8; e++) {
                int idx = lane * 8 + e;
                int r = idx >> 4, cc = idx & 15;
                C[(size_t)(gr0 + r) * DD + gc0 + cc] =
                    __float2half(stg[r * 16 + cc] + bias[gc0 + cc]);
            }
            __syncwarp();
        }
}

// ---------------------------------------------------------------------------
// Masked projection of X (half): Y[b][kc][d] = isl * sum_{s<len} P[s][kc]*X[b][s][d]
// M-tile 128 (kc), N-tile 128 (d), BK=16 (s), 8 warps (2m x 4n), warp 64x32
// ---------------------------------------------------------------------------
#define PJLD 136   // 128 + 8 halves

__global__ __launch_bounds__(256) void k_projX_h(
    const __half* __restrict__ Pk, const __half* __restrict__ Pv,
    const __half* __restrict__ X,
    __half* __restrict__ Yk, __half* __restrict__ Yv)
{
    __shared__ __half As[2][16 * PJLD];
    __shared__ __half Bs[2][16 * PJLD];
    __shared__ float  stgF[8 * 256];

    int zb = blockIdx.z;
    int z = zb >> 3, b = zb & 7;
    const __half* P = z ? Pv : Pk;
    __half* Y = (z ? Yv : Yk) + (size_t)b * KK * DD;
    const __half* Xb = X + (size_t)b * SS * DD;
    int m0 = blockIdx.y * 128;      // kc tile
    int n0 = blockIdx.x * 128;      // d tile
    int len = g_len[b];
    float isl = g_isl[b];

    int tid = threadIdx.x;
    int warp = tid >> 5, lane = tid & 31;
    int wm = warp & 1, wn = warp >> 1;   // 2 m-warps x 4 n-warps

    wmma::fragment<wmma::accumulator, 16, 16, 16, float> acc[4][2];
#pragma unroll
    for (int i = 0; i < 4; i++)
#pragma unroll
        for (int j = 0; j < 2; j++)
            wmma::fill_fragment(acc[i][j], 0.0f);

    auto load_stage = [&](int st, int s0) {
        // A: P[s0:s0+16, m0:m0+128] -> As[ss][kc], zero when s >= len
        // 16 rows x 16 chunks = 256 chunks; B identical shape
        int ss = tid >> 4, c8 = tid & 15;
        int s = s0 + ss;
        cp16p(&As[st][ss * PJLD + c8 * 8], &P[(size_t)s * KK + m0 + c8 * 8], s < len);
        cp16p(&Bs[st][ss * PJLD + c8 * 8], &Xb[(size_t)s * DD + n0 + c8 * 8], s < len);
        cp_commit();
    };

    int nsteps = (len + 15) >> 4;
    load_stage(0, 0);

    for (int st = 0; st < nsteps; st++) {
        int cur = st & 1;
        if (st + 1 < nsteps) { load_stage(cur ^ 1, (st + 1) * 16); cp_wait<1>(); }
        else                 { cp_wait<0>(); }
        __syncthreads();

        wmma::fragment<wmma::matrix_a, 16, 16, 16, __half, wmma::col_major> af[4];
        wmma::fragment<wmma::matrix_b, 16, 16, 16, __half, wmma::row_major> bf[2];
#pragma unroll
        for (int i = 0; i < 4; i++)
            wmma::load_matrix_sync(af[i], &As[cur][wm * 64 + i * 16], PJLD);
#pragma unroll
        for (int j = 0; j < 2; j++)
            wmma::load_matrix_sync(bf[j], &Bs[cur][wn * 32 + j * 16], PJLD);
#pragma unroll
        for (int i = 0; i < 4; i++)
#pragma unroll
            for (int j = 0; j < 2; j++)
                wmma::mma_sync(acc[i][j], af[i], bf[j], acc[i][j]);
        __syncthreads();
    }

    float* stg = stgF + warp * 256;
#pragma unroll
    for (int i = 0; i < 4; i++)
#pragma unroll
        for (int j = 0; j < 2; j++) {
            wmma::store_matrix_sync(stg, acc[i][j], 16, wmma::mem_row_major);
            __syncwarp();
            int gr0 = m0 + wm * 64 + i * 16;
            int gc0 = n0 + wn * 32 + j * 16;
#pragma unroll
            for (int e = 0; e < 8; e++) {
                int idx = lane * 8 + e;
                int r = idx >> 4, cc = idx & 15;
                Y[(size_t)(gr0 + r) * DD + gc0 + cc] =
                    __float2half(stg[r * 16 + cc] * isl);
            }
            __syncwarp();
        }
}

// ---------------------------------------------------------------------------
// Small GEMM (half): O_z[b] = Y_z[b] @ W_z^T + colsum (x) bias, output half
// ---------------------------------------------------------------------------
__global__ __launch_bounds__(128, 2) void k_gemm2_h(
    const __half* __restrict__ Yk, const __half* __restrict__ Yv,
    const __half* __restrict__ Wk, const float* __restrict__ bk,
    const __half* __restrict__ Wv, const float* __restrict__ bv,
    __half* __restrict__ Ok, __half* __restrict__ Ov)
{
    __shared__ __half As[2][128 * HLD];
    __shared__ __half Bs[2][128 * HLD];
    __shared__ float  stgF[4 * 256];

    int zb = blockIdx.z;
    int z = zb >> 3, b = zb & 7;
    const __half* A = (z ? Yv : Yk) + (size_t)b * KK * DD;
    const __half* W = z ? Wv : Wk;
    const float* bias = z ? bv : bk;
    __half* C = (z ? Ov : Ok) + (size_t)b * KK * DD;
    const float* cs = g_colsum + (z * BB + b) * KK;

    int tid = threadIdx.x;
    int warp = tid >> 5, lane = tid & 31;
    int wm = warp & 1, wn = warp >> 1;
    int m0 = blockIdx.y * 128, n0 = blockIdx.x * 128;

    wmma::fragment<wmma::accumulator, 16, 16, 16, float> acc[4][4];
#pragma unroll
    for (int i = 0; i < 4; i++)
#pragma unroll
        for (int j = 0; j < 4; j++)
            wmma::fill_fragment(acc[i][j], 0.0f);

    auto load_stage = [&](int st, int k0) {
#pragma unroll
        for (int it = 0; it < 4; it++) {
            int c = tid + it * 128;
            int row = c >> 2, c8 = c & 3;
            cp16(&As[st][row * HLD + c8 * 8], &A[(size_t)(m0 + row) * DD + k0 + c8 * 8]);
            cp16(&Bs[st][row * HLD + c8 * 8], &W[(size_t)(n0 + row) * DD + k0 + c8 * 8]);
        }
        cp_commit();
    };

    load_stage(0, 0);
    const int NK0 = DD / 32;
    for (int k0i = 0; k0i < NK0; k0i++) {
        int cur = k0i & 1;
        if (k0i + 1 < NK0) { load_stage(cur ^ 1, (k0i + 1) * 32); cp_wait<1>(); }
        else               { cp_wait<0>(); }
        __syncthreads();

#pragma unroll
        for (int ksub = 0; ksub < 2; ksub++) {
            wmma::fragment<wmma::matrix_a, 16, 16, 16, __half, wmma::row_major> af[4];
            wmma::fragment<wmma::matrix_b, 16, 16, 16, __half, wmma::col_major> bf[4];
#pragma unroll
            for (int i = 0; i < 4; i++)
                wmma::load_matrix_sync(af[i], &As[cur][(wm * 64 + i * 16) * HLD + ksub * 16], HLD);
#pragma unroll
            for (int j = 0; j < 4; j++)
                wmma::load_matrix_sync(bf[j], &Bs[cur][(wn * 64 + j * 16) * HLD + ksub * 16], HLD);
#pragma unroll
            for (int i = 0; i < 4; i++)
#pragma unroll
                for (int j = 0; j < 4; j++)
                    wmma::mma_sync(acc[i][j], af[i], bf[j], acc[i][j]);
        }
        __syncthreads();
    }

    float* stg = stgF + warp * 256;
#pragma unroll
    for (int i = 0; i < 4; i++)
#pragma unroll
        for (int j = 0; j < 4; j++) {
            wmma::store_matrix_sync(stg, acc[i][j], 16, wmma::mem_row_major);
            __syncwarp();
            int gr0 = m0 + wm * 64 + i * 16;
            int gc0 = n0 + wn * 64 + j * 16;
#pragma unroll
            for (int e = 0; e < 8; e++) {
                int idx = lane * 8 + e;
                int r = idx >> 4, cc = idx & 15;
                C[(size_t)(gr0 + r) * DD + gc0 + cc] =
                    __float2half(stg[r * 16 + cc] + cs[gr0 + r] * bias[gc0 + cc]);
            }
            __syncwarp();
        }
}

// ---------------------------------------------------------------------------
// Attention (half MMA inputs): per (b, h, 64-query tile)
// scores fp32 in smem -> softmax fp32 -> probs half -> ctx fp32 out
// smem: K[256][72]h + V[256][72]h + S[64][264]f + P[64][264]h = 171 KB
// ---------------------------------------------------------------------------
#define KVP 72    // 64 + 8 halves
#define SLD 264   // fp32 score row
#define PLD2 264  // half prob row

__global__ __launch_bounds__(256, 1) void k_attn_h(
    const __half* __restrict__ q, const __half* __restrict__ kp,
    const __half* __restrict__ vp, float* __restrict__ out)
{
    extern __shared__ char smraw[];
    __half* ks = (__half*)smraw;                       // [KK][KVP]
    __half* vs = ks + KK * KVP;                        // [KK][KVP]
    float*  sc = (float*)(vs + KK * KVP);              // [64][SLD]
    __half* ph = (__half*)(sc + 64 * SLD);             // [64][PLD2]

    int qt = blockIdx.x, h = blockIdx.y, b = blockIdx.z;
    int s0 = qt * 64;
    int tid = threadIdx.x;
    int warp = tid >> 5;

    // Load K/V tiles: 256 rows x 64 halves (8 chunks of 8 halves per row)
    for (int i = tid; i < KK * 8; i += 256) {
        int r = i >> 3, c8 = i & 7;
        size_t off = ((size_t)b * KK + r) * DD + h * DH + c8 * 8;
        *(float4*)&ks[r * KVP + c8 * 8] = *(const float4*)&kp[off];
        *(float4*)&vs[r * KVP + c8 * 8] = *(const float4*)&vp[off];
    }
    __syncthreads();

    // Phase A: scores = Q @ K^T (Q fragments straight from gmem half)
    {
        const __half* qg = q + ((size_t)b * SS + s0) * DD + h * DH;
        int n0w = warp * 32;
        wmma::fragment<wmma::accumulator, 16, 16, 16, float> accs[4][2];
#pragma unroll
        for (int i = 0; i < 4; i++)
#pragma unroll
            for (int j = 0; j < 2; j++)
                wmma::fill_fragment(accs[i][j], 0.0f);

#pragma unroll
        for (int k16 = 0; k16 < DH / 16; k16++) {
            wmma::fragment<wmma::matrix_a, 16, 16, 16, __half, wmma::row_major> af[4];
            wmma::fragment<wmma::matrix_b, 16, 16, 16, __half, wmma::col_major> bf[2];
#pragma unroll
            for (int i = 0; i < 4; i++)
                wmma::load_matrix_sync(af[i], qg + (size_t)(i * 16) * DD + k16 * 16, DD);
#pragma unroll
            for (int j = 0; j < 2; j++)
                wmma::load_matrix_sync(bf[j], &ks[(n0w + j * 16) * KVP + k16 * 16], KVP);
#pragma unroll
            for (int i = 0; i < 4; i++)
#pragma unroll
                for (int j = 0; j < 2; j++)
                    wmma::mma_sync(accs[i][j], af[i], bf[j], accs[i][j]);
        }
#pragma unroll
        for (int i = 0; i < 4; i++)
#pragma unroll
            for (int j = 0; j < 2; j++)
                wmma::store_matrix_sync(&sc[(i * 16) * SLD + n0w + j * 16],
                                        accs[i][j], SLD, wmma::mem_row_major);
    }
    __syncthreads();

    // Phase B: fp32 softmax per row, write half probs
    if (tid < 64) {
        float* row = &sc[tid * SLD];
        __half* prow = &ph[tid * PLD2];
        float mx = -3.0e38f;
#pragma unroll 4
        for (int k = 0; k < KK; k++) mx = fmaxf(mx, row[k]);
        float sum = 0.f;
#pragma unroll 4
        for (int k = 0; k < KK; k++) {
            float e = __expf((row[k] - mx) * 0.125f);
            row[k] = e;
            sum += e;
        }
        float inv = 1.0f / sum;
#pragma unroll 4
        for (int k = 0; k < KK; k++)
            prow[k] = __float2half(row[k] * inv);
    }
    __syncthreads();

    // Phase C: ctx = P @ V (half MMA, fp32 out)
    {
        int wm = warp & 1, wn = warp >> 1;
        wmma::fragment<wmma::accumulator, 16, 16, 16, float> accc[2];
        wmma::fill_fragment(accc[0], 0.0f);
        wmma::fill_fragment(accc[1], 0.0f);

#pragma unroll 4
        for (int k16 = 0; k16 < KK / 16; k16++) {
            wmma::fragment<wmma::matrix_a, 16, 16, 16, __half, wmma::row_major> af[2];
            wmma::fragment<wmma::matrix_b, 16, 16, 16, __half, wmma::row_major> bf;
#pragma unroll
            for (int i = 0; i < 2; i++)
                wmma::load_matrix_sync(af[i], &ph[(wm * 32 + i * 16) * PLD2 + k16 * 16], PLD2);
            wmma::load_matrix_sync(bf, &vs[(k16 * 16) * KVP + wn * 16], KVP);
#pragma unroll
            for (int i = 0; i < 2; i++)
                wmma::mma_sync(accc[i], af[i], bf, accc[i]);
        }

#pragma unroll
        for (int i = 0; i < 2; i++) {
            float* dst = out + ((size_t)b * SS + s0 + wm * 32 + i * 16) * DD + h * DH + wn * 16;
            wmma::store_matrix_sync(dst, accc[i], DD, wmma::mem_row_major);
        }
    }
}

// ---------------------------------------------------------------------------
extern "C" void kernel_launch(void* const* d_in, const int* in_sizes, int n_in,
                              void* d_out, int out_size)
{
    const float* X    = (const float*)d_in[0];
    const float* mask = (const float*)d_in[1];
    const float* Wq   = (const float*)d_in[2];
    const float* bq   = (const float*)d_in[3];
    const float* Wk   = (const float*)d_in[4];
    const float* bk   = (const float*)d_in[5];
    const float* Wv   = (const float*)d_in[6];
    const float* bv   = (const float*)d_in[7];
    const float* pk   = (const float*)d_in[8];
    const float* pv   = (const float*)d_in[9];
    float* out = (float*)d_out;

    __half *Xh, *Wqh, *Wkh, *Wvh, *Pkh, *Pvh, *qh, *yk, *yv, *hkp, *hvp;
    cudaGetSymbolAddress((void**)&Xh,  g_Xh);
    cudaGetSymbolAddress((void**)&Wqh, g_Wqh);
    cudaGetSymbolAddress((void**)&Wkh, g_Wkh);
    cudaGetSymbolAddress((void**)&Wvh, g_Wvh);
    cudaGetSymbolAddress((void**)&Pkh, g_Pkh);
    cudaGetSymbolAddress((void**)&Pvh, g_Pvh);
    cudaGetSymbolAddress((void**)&qh,  g_qh);
    cudaGetSymbolAddress((void**)&yk,  g_yk);
    cudaGetSymbolAddress((void**)&yv,  g_yv);
    cudaGetSymbolAddress((void**)&hkp, g_hkp);
    cudaGetSymbolAddress((void**)&hvp, g_hvp);

    const int ATTN_SMEM = KK * KVP * 2 * 2 + 64 * SLD * 4 + 64 * PLD2 * 2;  // ~171 KB
    cudaFuncSetAttribute(k_attn_h, cudaFuncAttributeMaxDynamicSharedMemorySize, ATTN_SMEM);

    k_lengths<<<BB, 256>>>(mask);
    k_colsum<<<dim3(2, BB), KK>>>(pk, pv);

    // fp32 -> fp16 conversions
    k_f2h<<<(size_t)MM * DD / 8 / 256, 256>>>(X,  Xh,  (size_t)MM * DD);
    k_f2h<<<DD * DD / 8 / 256, 256>>>(Wq, Wqh, (size_t)DD * DD);
    k_f2h<<<DD * DD / 8 / 256, 256>>>(Wk, Wkh, (size_t)DD * DD);
    k_f2h<<<DD * DD / 8 / 256, 256>>>(Wv, Wvh, (size_t)DD * DD);
    k_f2h<<<SS * KK / 8 / 256, 256>>>(pk, Pkh, (size_t)SS * KK);
    k_f2h<<<SS * KK / 8 / 256, 256>>>(pv, Pvh, (size_t)SS * KK);

    // Y_z = isl * P_z'^T @ X   (256 CTAs)
    k_projX_h<<<dim3(DD / 128, KK / 128, 16), 256>>>(Pkh, Pvh, Xh, yk, yv);

    // hkp/hvp = Y_z @ W_z^T + colsum (x) bias
    k_gemm2_h<<<dim3(DD / 128, KK / 128, 16), 128>>>(yk, yv, Wkh, bk, Wvh, bv, hkp, hvp);

    // Q projection
    k_qgemm_h<<<dim3(DD / 128, MM / 128), 128>>>(Xh, Wqh, bq, qh);

    k_attn_h<<<dim3(SS / 64, HH, BB), 256, ATTN_SMEM>>>(qh, hkp, hvp, out);
}

// round 10
// speedup vs baseline: 5.6524x; 1.6452x over previous
#include <cuda_runtime.h>
#include <cuda_fp16.h>
#include <mma.h>

using namespace nvcuda;

#define BB 8
#define SS 4096
#define DD 1024
#define HH 16
#define KK 256
#define DH 64
#define MM (BB*SS)

// Scratch (device globals)
__device__ __half g_Xh [(size_t)MM * DD];
__device__ __half g_Wqh[(size_t)DD * DD];
__device__ __half g_Wkh[(size_t)DD * DD];
__device__ __half g_Wvh[(size_t)DD * DD];
__device__ __half g_Pkh[(size_t)SS * KK];
__device__ __half g_Pvh[(size_t)SS * KK];
__device__ __half g_qh [(size_t)MM * DD];
__device__ __half g_yk [(size_t)BB * KK * DD];
__device__ __half g_yv [(size_t)BB * KK * DD];
__device__ __half g_hkp[(size_t)BB * KK * DD];
__device__ __half g_hvp[(size_t)BB * KK * DD];
__device__ float  g_colsum[2 * BB * KK];
__device__ int    g_len[BB];
__device__ float  g_isl[BB];

// ---------------------------------------------------------------------------
__global__ void k_lengths(const float* __restrict__ mask) {
    int b = blockIdx.x;
    __shared__ int cnt;
    if (threadIdx.x == 0) cnt = 0;
    __syncthreads();
    int local = 0;
    for (int s = threadIdx.x; s < SS; s += blockDim.x)
        if (mask[(size_t)b * SS + s] > -1.0f) local++;
    atomicAdd(&cnt, local);
    __syncthreads();
    if (threadIdx.x == 0) {
        g_len[b] = cnt;
        g_isl[b] = rsqrtf((float)cnt);
    }
}

__global__ void k_colsum(const float* __restrict__ Pk, const float* __restrict__ Pv) {
    int z = blockIdx.x, b = blockIdx.y;
    int kc = threadIdx.x;
    const float* P = z ? Pv : Pk;
    int len = g_len[b];
    float s = 0.f;
    for (int i = 0; i < len; i++) s += P[(size_t)i * KK + kc];
    g_colsum[(z * BB + b) * KK + kc] = s * g_isl[b];
}

__global__ void k_f2h(const float* __restrict__ s, __half* __restrict__ d, size_t n) {
    size_t i = ((size_t)blockIdx.x * blockDim.x + threadIdx.x) * 8;
    if (i >= n) return;
    float4 a = *(const float4*)&s[i];
    float4 b = *(const float4*)&s[i + 4];
    __half2* dp = (__half2*)&d[i];
    dp[0] = __floats2half2_rn(a.x, a.y);
    dp[1] = __floats2half2_rn(a.z, a.w);
    dp[2] = __floats2half2_rn(b.x, b.y);
    dp[3] = __floats2half2_rn(b.z, b.w);
}

// ---------------------------------------------------------------------------
__device__ __forceinline__ void cp16(void* smem_dst, const void* gsrc) {
    unsigned saddr = (unsigned)__cvta_generic_to_shared(smem_dst);
    asm volatile("cp.async.cg.shared.global [%0], [%1], 16;\n" :: "r"(saddr), "l"(gsrc));
}
__device__ __forceinline__ void cp16p(void* smem_dst, const void* gsrc, bool valid) {
    unsigned saddr = (unsigned)__cvta_generic_to_shared(smem_dst);
    int sz = valid ? 16 : 0;
    asm volatile("cp.async.cg.shared.global [%0], [%1], 16, %2;\n"
                 :: "r"(saddr), "l"(gsrc), "r"(sz));
}
__device__ __forceinline__ void cp_commit() {
    asm volatile("cp.async.commit_group;\n");
}
template<int N> __device__ __forceinline__ void cp_wait() {
    asm volatile("cp.async.wait_group %0;\n" :: "n"(N));
}

// ---------------------------------------------------------------------------
// Q GEMM (half): 3-stage cp.async ring, 128x128 block, 4 warps, warp 64x64
// ---------------------------------------------------------------------------
#define HLD 40

__global__ __launch_bounds__(128, 2) void k_qgemm_h(
    const __half* __restrict__ X, const __half* __restrict__ W,
    const float* __restrict__ bias, __half* __restrict__ C)
{
    __shared__ __half As[3][128 * HLD];
    __shared__ __half Bs[3][128 * HLD];
    __shared__ float  stgF[4 * 256];

    int tid = threadIdx.x;
    int warp = tid >> 5, lane = tid & 31;
    int wm = warp & 1, wn = warp >> 1;
    int m0 = blockIdx.y * 128, n0 = blockIdx.x * 128;

    wmma::fragment<wmma::accumulator, 16, 16, 16, float> acc[4][4];
#pragma unroll
    for (int i = 0; i < 4; i++)
#pragma unroll
        for (int j = 0; j < 4; j++)
            wmma::fill_fragment(acc[i][j], 0.0f);

    auto load_stage = [&](int st, int k0) {
#pragma unroll
        for (int it = 0; it < 4; it++) {
            int c = tid + it * 128;
            int row = c >> 2, c8 = c & 3;
            cp16(&As[st][row * HLD + c8 * 8], &X[(size_t)(m0 + row) * DD + k0 + c8 * 8]);
            cp16(&Bs[st][row * HLD + c8 * 8], &W[(size_t)(n0 + row) * DD + k0 + c8 * 8]);
        }
        cp_commit();
    };

    load_stage(0, 0);
    load_stage(1, 32);

    const int NK0 = DD / 32;
    for (int k0i = 0; k0i < NK0; k0i++) {
        int cur = k0i % 3;
        if (k0i + 2 < NK0) { load_stage((k0i + 2) % 3, (k0i + 2) * 32); cp_wait<2>(); }
        else if (k0i + 1 < NK0) { cp_wait<1>(); }
        else { cp_wait<0>(); }
        __syncthreads();

#pragma unroll
        for (int ksub = 0; ksub < 2; ksub++) {
            wmma::fragment<wmma::matrix_a, 16, 16, 16, __half, wmma::row_major> af[4];
            wmma::fragment<wmma::matrix_b, 16, 16, 16, __half, wmma::col_major> bf[4];
#pragma unroll
            for (int i = 0; i < 4; i++)
                wmma::load_matrix_sync(af[i], &As[cur][(wm * 64 + i * 16) * HLD + ksub * 16], HLD);
#pragma unroll
            for (int j = 0; j < 4; j++)
                wmma::load_matrix_sync(bf[j], &Bs[cur][(wn * 64 + j * 16) * HLD + ksub * 16], HLD);
#pragma unroll
            for (int i = 0; i < 4; i++)
#pragma unroll
                for (int j = 0; j < 4; j++)
                    wmma::mma_sync(acc[i][j], af[i], bf[j], acc[i][j]);
        }
        __syncthreads();
    }

    float* stg = stgF + warp * 256;
#pragma unroll
    for (int i = 0; i < 4; i++)
#pragma unroll
        for (int j = 0; j < 4; j++) {
            wmma::store_matrix_sync(stg, acc[i][j], 16, wmma::mem_row_major);
            __syncwarp();
            int gr0 = m0 + wm * 64 + i * 16;
            int gc0 = n0 + wn * 64 + j * 16;
#pragma unroll
            for (int e = 0; e < 8; e++) {
                int idx = lane * 8 + e;
                int r = idx >> 4, cc = idx & 15;
                C[(size_t)(gr0 + r) * DD + gc0 + cc] =
                    __float2half(stg[r * 16 + cc] + bias[gc0 + cc]);
            }
            __syncwarp();
        }
}

// ---------------------------------------------------------------------------
// Masked projection of X (half) — unchanged from R8
// ---------------------------------------------------------------------------
#define PJLD 136

__global__ __launch_bounds__(256) void k_projX_h(
    const __half* __restrict__ Pk, const __half* __restrict__ Pv,
    const __half* __restrict__ X,
    __half* __restrict__ Yk, __half* __restrict__ Yv)
{
    __shared__ __half As[2][16 * PJLD];
    __shared__ __half Bs[2][16 * PJLD];
    __shared__ float  stgF[8 * 256];

    int zb = blockIdx.z;
    int z = zb >> 3, b = zb & 7;
    const __half* P = z ? Pv : Pk;
    __half* Y = (z ? Yv : Yk) + (size_t)b * KK * DD;
    const __half* Xb = X + (size_t)b * SS * DD;
    int m0 = blockIdx.y * 128;
    int n0 = blockIdx.x * 128;
    int len = g_len[b];
    float isl = g_isl[b];

    int tid = threadIdx.x;
    int warp = tid >> 5, lane = tid & 31;
    int wm = warp & 1, wn = warp >> 1;

    wmma::fragment<wmma::accumulator, 16, 16, 16, float> acc[4][2];
#pragma unroll
    for (int i = 0; i < 4; i++)
#pragma unroll
        for (int j = 0; j < 2; j++)
            wmma::fill_fragment(acc[i][j], 0.0f);

    auto load_stage = [&](int st, int s0) {
        int ss = tid >> 4, c8 = tid & 15;
        int s = s0 + ss;
        cp16p(&As[st][ss * PJLD + c8 * 8], &P[(size_t)s * KK + m0 + c8 * 8], s < len);
        cp16p(&Bs[st][ss * PJLD + c8 * 8], &Xb[(size_t)s * DD + n0 + c8 * 8], s < len);
        cp_commit();
    };

    int nsteps = (len + 15) >> 4;
    load_stage(0, 0);

    for (int st = 0; st < nsteps; st++) {
        int cur = st & 1;
        if (st + 1 < nsteps) { load_stage(cur ^ 1, (st + 1) * 16); cp_wait<1>(); }
        else                 { cp_wait<0>(); }
        __syncthreads();

        wmma::fragment<wmma::matrix_a, 16, 16, 16, __half, wmma::col_major> af[4];
        wmma::fragment<wmma::matrix_b, 16, 16, 16, __half, wmma::row_major> bf[2];
#pragma unroll
        for (int i = 0; i < 4; i++)
            wmma::load_matrix_sync(af[i], &As[cur][wm * 64 + i * 16], PJLD);
#pragma unroll
        for (int j = 0; j < 2; j++)
            wmma::load_matrix_sync(bf[j], &Bs[cur][wn * 32 + j * 16], PJLD);
#pragma unroll
        for (int i = 0; i < 4; i++)
#pragma unroll
            for (int j = 0; j < 2; j++)
                wmma::mma_sync(acc[i][j], af[i], bf[j], acc[i][j]);
        __syncthreads();
    }

    float* stg = stgF + warp * 256;
#pragma unroll
    for (int i = 0; i < 4; i++)
#pragma unroll
        for (int j = 0; j < 2; j++) {
            wmma::store_matrix_sync(stg, acc[i][j], 16, wmma::mem_row_major);
            __syncwarp();
            int gr0 = m0 + wm * 64 + i * 16;
            int gc0 = n0 + wn * 32 + j * 16;
#pragma unroll
            for (int e = 0; e < 8; e++) {
                int idx = lane * 8 + e;
                int r = idx >> 4, cc = idx & 15;
                Y[(size_t)(gr0 + r) * DD + gc0 + cc] =
                    __float2half(stg[r * 16 + cc] * isl);
            }
            __syncwarp();
        }
}

// ---------------------------------------------------------------------------
// Small GEMM (half) — unchanged from R8
// ---------------------------------------------------------------------------
__global__ __launch_bounds__(128, 2) void k_gemm2_h(
    const __half* __restrict__ Yk, const __half* __restrict__ Yv,
    const __half* __restrict__ Wk, const float* __restrict__ bk,
    const __half* __restrict__ Wv, const float* __restrict__ bv,
    __half* __restrict__ Ok, __half* __restrict__ Ov)
{
    __shared__ __half As[2][128 * HLD];
    __shared__ __half Bs[2][128 * HLD];
    __shared__ float  stgF[4 * 256];

    int zb = blockIdx.z;
    int z = zb >> 3, b = zb & 7;
    const __half* A = (z ? Yv : Yk) + (size_t)b * KK * DD;
    const __half* W = z ? Wv : Wk;
    const float* bias = z ? bv : bk;
    __half* C = (z ? Ov : Ok) + (size_t)b * KK * DD;
    const float* cs = g_colsum + (z * BB + b) * KK;

    int tid = threadIdx.x;
    int warp = tid >> 5, lane = tid & 31;
    int wm = warp & 1, wn = warp >> 1;
    int m0 = blockIdx.y * 128, n0 = blockIdx.x * 128;

    wmma::fragment<wmma::accumulator, 16, 16, 16, float> acc[4][4];
#pragma unroll
    for (int i = 0; i < 4; i++)
#pragma unroll
        for (int j = 0; j < 4; j++)
            wmma::fill_fragment(acc[i][j], 0.0f);

    auto load_stage = [&](int st, int k0) {
#pragma unroll
        for (int it = 0; it < 4; it++) {
            int c = tid + it * 128;
            int row = c >> 2, c8 = c & 3;
            cp16(&As[st][row * HLD + c8 * 8], &A[(size_t)(m0 + row) * DD + k0 + c8 * 8]);
            cp16(&Bs[st][row * HLD + c8 * 8], &W[(size_t)(n0 + row) * DD + k0 + c8 * 8]);
        }
        cp_commit();
    };

    load_stage(0, 0);
    const int NK0 = DD / 32;
    for (int k0i = 0; k0i < NK0; k0i++) {
        int cur = k0i & 1;
        if (k0i + 1 < NK0) { load_stage(cur ^ 1, (k0i + 1) * 32); cp_wait<1>(); }
        else               { cp_wait<0>(); }
        __syncthreads();

#pragma unroll
        for (int ksub = 0; ksub < 2; ksub++) {
            wmma::fragment<wmma::matrix_a, 16, 16, 16, __half, wmma::row_major> af[4];
            wmma::fragment<wmma::matrix_b, 16, 16, 16, __half, wmma::col_major> bf[4];
#pragma unroll
            for (int i = 0; i < 4; i++)
                wmma::load_matrix_sync(af[i], &As[cur][(wm * 64 + i * 16) * HLD + ksub * 16], HLD);
#pragma unroll
            for (int j = 0; j < 4; j++)
                wmma::load_matrix_sync(bf[j], &Bs[cur][(wn * 64 + j * 16) * HLD + ksub * 16], HLD);
#pragma unroll
            for (int i = 0; i < 4; i++)
#pragma unroll
                for (int j = 0; j < 4; j++)
                    wmma::mma_sync(acc[i][j], af[i], bf[j], acc[i][j]);
        }
        __syncthreads();
    }

    float* stg = stgF + warp * 256;
#pragma unroll
    for (int i = 0; i < 4; i++)
#pragma unroll
        for (int j = 0; j < 4; j++) {
            wmma::store_matrix_sync(stg, acc[i][j], 16, wmma::mem_row_major);
            __syncwarp();
            int gr0 = m0 + wm * 64 + i * 16;
            int gc0 = n0 + wn * 64 + j * 16;
#pragma unroll
            for (int e = 0; e < 8; e++) {
                int idx = lane * 8 + e;
                int r = idx >> 4, cc = idx & 15;
                C[(size_t)(gr0 + r) * DD + gc0 + cc] =
                    __float2half(stg[r * 16 + cc] + cs[gr0 + r] * bias[gc0 + cc]);
            }
            __syncwarp();
        }
}

// ---------------------------------------------------------------------------
// Attention v2: 2 CTAs/SM.
//   smem: KV buffer [256][72]h (36.9KB, K then V) + scores [64][264]f (67.6KB)
//   Phase A: scores = Q@K^T (Q frags from gmem)
//   Phase B: all-256-thread softmax; probs written as half IN PLACE over the
//            low bytes of each fp32 score row (safe via register staging)
//   Phase C: V loaded into KV buffer, ctx = P@V
// ---------------------------------------------------------------------------
#define KVP 72
#define SCLD 264

__global__ __launch_bounds__(256, 2) void k_attn_h(
    const __half* __restrict__ q, const __half* __restrict__ kp,
    const __half* __restrict__ vp, float* __restrict__ out)
{
    extern __shared__ char smraw[];
    __half* kv = (__half*)smraw;                 // [KK][KVP]
    float*  sc = (float*)(kv + KK * KVP);        // [64][SCLD]

    int qt = blockIdx.x, h = blockIdx.y, b = blockIdx.z;
    int s0 = qt * 64;
    int tid = threadIdx.x;
    int warp = tid >> 5, lane = tid & 31;

    // Load K tile only
    for (int i = tid; i < KK * 8; i += 256) {
        int r = i >> 3, c8 = i & 7;
        *(float4*)&kv[r * KVP + c8 * 8] =
            *(const float4*)&kp[((size_t)b * KK + r) * DD + h * DH + c8 * 8];
    }
    __syncthreads();

    // Phase A: scores = Q @ K^T; warp owns score cols [warp*32, warp*32+32)
    {
        const __half* qg = q + ((size_t)b * SS + s0) * DD + h * DH;
        int n0w = warp * 32;
        wmma::fragment<wmma::accumulator, 16, 16, 16, float> accs[4][2];
#pragma unroll
        for (int i = 0; i < 4; i++)
#pragma unroll
            for (int j = 0; j < 2; j++)
                wmma::fill_fragment(accs[i][j], 0.0f);

#pragma unroll
        for (int k16 = 0; k16 < DH / 16; k16++) {
            wmma::fragment<wmma::matrix_a, 16, 16, 16, __half, wmma::row_major> af[4];
            wmma::fragment<wmma::matrix_b, 16, 16, 16, __half, wmma::col_major> bf[2];
#pragma unroll
            for (int i = 0; i < 4; i++)
                wmma::load_matrix_sync(af[i], qg + (size_t)(i * 16) * DD + k16 * 16, DD);
#pragma unroll
            for (int j = 0; j < 2; j++)
                wmma::load_matrix_sync(bf[j], &kv[(n0w + j * 16) * KVP + k16 * 16], KVP);
#pragma unroll
            for (int i = 0; i < 4; i++)
#pragma unroll
                for (int j = 0; j < 2; j++)
                    wmma::mma_sync(accs[i][j], af[i], bf[j], accs[i][j]);
        }
#pragma unroll
        for (int i = 0; i < 4; i++)
#pragma unroll
            for (int j = 0; j < 2; j++)
                wmma::store_matrix_sync(&sc[(i * 16) * SCLD + n0w + j * 16],
                                        accs[i][j], SCLD, wmma::mem_row_major);
    }
    __syncthreads();

    // Phase B: softmax, 4 threads per row (row = warp*8 + lane/4, cols lane%4 * 64)
    {
        int row = warp * 8 + (lane >> 2);
        int c0 = (lane & 3) * 64;
        float* rp = &sc[row * SCLD + c0];
        float v[64];
#pragma unroll
        for (int i = 0; i < 16; i++)
            *(float4*)&v[i * 4] = *(const float4*)&rp[i * 4];

        float mx = v[0];
#pragma unroll
        for (int i = 1; i < 64; i++) mx = fmaxf(mx, v[i]);
        mx = fmaxf(mx, __shfl_xor_sync(0xffffffffu, mx, 1));
        mx = fmaxf(mx, __shfl_xor_sync(0xffffffffu, mx, 2));

        float sum = 0.f;
#pragma unroll
        for (int i = 0; i < 64; i++) {
            v[i] = __expf((v[i] - mx) * 0.125f);
            sum += v[i];
        }
        sum += __shfl_xor_sync(0xffffffffu, sum, 1);
        sum += __shfl_xor_sync(0xffffffffu, sum, 2);
        float inv = 1.0f / sum;

        // write half probs in place at row base (bytes [0, 512) of the row)
        __half2* pw = (__half2*)((__half*)&sc[row * SCLD] + c0);
#pragma unroll
        for (int i = 0; i < 32; i++)
            pw[i] = __floats2half2_rn(v[2 * i] * inv, v[2 * i + 1] * inv);
    }
    __syncthreads();

    // Load V tile into kv buffer (K is dead now)
    for (int i = tid; i < KK * 8; i += 256) {
        int r = i >> 3, c8 = i & 7;
        *(float4*)&kv[r * KVP + c8 * 8] =
            *(const float4*)&vp[((size_t)b * KK + r) * DD + h * DH + c8 * 8];
    }
    __syncthreads();

    // Phase C: ctx = P @ V.  Warps: wm in {0,1} (32 rows), wn in {0..3} (16 cols)
    {
        int wm = warp & 1, wn = warp >> 1;
        const __half* ph = (const __half*)sc;    // probs, row stride SCLD*2 halves
        wmma::fragment<wmma::accumulator, 16, 16, 16, float> accc[2];
        wmma::fill_fragment(accc[0], 0.0f);
        wmma::fill_fragment(accc[1], 0.0f);

#pragma unroll 4
        for (int k16 = 0; k16 < KK / 16; k16++) {
            wmma::fragment<wmma::matrix_a, 16, 16, 16, __half, wmma::row_major> af[2];
            wmma::fragment<wmma::matrix_b, 16, 16, 16, __half, wmma::row_major> bf;
#pragma unroll
            for (int i = 0; i < 2; i++)
                wmma::load_matrix_sync(af[i], ph + (size_t)(wm * 32 + i * 16) * (SCLD * 2) + k16 * 16,
                                       SCLD * 2);
            wmma::load_matrix_sync(bf, &kv[(k16 * 16) * KVP + wn * 16], KVP);
#pragma unroll
            for (int i = 0; i < 2; i++)
                wmma::mma_sync(accc[i], af[i], bf, accc[i]);
        }

#pragma unroll
        for (int i = 0; i < 2; i++) {
            float* dst = out + ((size_t)b * SS + s0 + wm * 32 + i * 16) * DD + h * DH + wn * 16;
            wmma::store_matrix_sync(dst, accc[i], DD, wmma::mem_row_major);
        }
    }
}

// ---------------------------------------------------------------------------
extern "C" void kernel_launch(void* const* d_in, const int* in_sizes, int n_in,
                              void* d_out, int out_size)
{
    const float* X    = (const float*)d_in[0];
    const float* mask = (const float*)d_in[1];
    const float* Wq   = (const float*)d_in[2];
    const float* bq   = (const float*)d_in[3];
    const float* Wk   = (const float*)d_in[4];
    const float* bk   = (const float*)d_in[5];
    const float* Wv   = (const float*)d_in[6];
    const float* bv   = (const float*)d_in[7];
    const float* pk   = (const float*)d_in[8];
    const float* pv   = (const float*)d_in[9];
    float* out = (float*)d_out;

    __half *Xh, *Wqh, *Wkh, *Wvh, *Pkh, *Pvh, *qh, *yk, *yv, *hkp, *hvp;
    cudaGetSymbolAddress((void**)&Xh,  g_Xh);
    cudaGetSymbolAddress((void**)&Wqh, g_Wqh);
    cudaGetSymbolAddress((void**)&Wkh, g_Wkh);
    cudaGetSymbolAddress((void**)&Wvh, g_Wvh);
    cudaGetSymbolAddress((void**)&Pkh, g_Pkh);
    cudaGetSymbolAddress((void**)&Pvh, g_Pvh);
    cudaGetSymbolAddress((void**)&qh,  g_qh);
    cudaGetSymbolAddress((void**)&yk,  g_yk);
    cudaGetSymbolAddress((void**)&yv,  g_yv);
    cudaGetSymbolAddress((void**)&hkp, g_hkp);
    cudaGetSymbolAddress((void**)&hvp, g_hvp);

    const int ATTN_SMEM = KK * KVP * 2 + 64 * SCLD * 4;   // 36.9KB + 67.6KB = 104.5KB
    cudaFuncSetAttribute(k_attn_h, cudaFuncAttributeMaxDynamicSharedMemorySize, ATTN_SMEM);

    k_lengths<<<BB, 256>>>(mask);
    k_colsum<<<dim3(2, BB), KK>>>(pk, pv);

    k_f2h<<<(size_t)MM * DD / 8 / 256, 256>>>(X,  Xh,  (size_t)MM * DD);
    k_f2h<<<DD * DD / 8 / 256, 256>>>(Wq, Wqh, (size_t)DD * DD);
    k_f2h<<<DD * DD / 8 / 256, 256>>>(Wk, Wkh, (size_t)DD * DD);
    k_f2h<<<DD * DD / 8 / 256, 256>>>(Wv, Wvh, (size_t)DD * DD);
    k_f2h<<<SS * KK / 8 / 256, 256>>>(pk, Pkh, (size_t)SS * KK);
    k_f2h<<<SS * KK / 8 / 256, 256>>>(pv, Pvh, (size_t)SS * KK);

    k_projX_h<<<dim3(DD / 128, KK / 128, 16), 256>>>(Pkh, Pvh, Xh, yk, yv);
    k_gemm2_h<<<dim3(DD / 128, KK / 128, 16), 128>>>(yk, yv, Wkh, bk, Wvh, bv, hkp, hvp);
    k_qgemm_h<<<dim3(DD / 128, MM / 128), 128>>>(Xh, Wqh, bq, qh);

    k_attn_h<<<dim3(SS / 64, HH, BB), 256, ATTN_SMEM>>>(qh, hkp, hvp, out);
}